// round 11
// baseline (speedup 1.0000x reference)
#include <cuda_runtime.h>
#include <cuda_fp16.h>
#include <math.h>
#include <stdint.h>

// ---------------------------------------------------------------------------
// Problem constants
// ---------------------------------------------------------------------------
#define BSZ   4
#define TSEQ  2048
#define CEMB  1024
#define NH    16
#define HD    64
#define RKV   512
#define FF    4096
#define MROWS (BSZ * TSEQ)   // 8192

typedef __half hf;

// ---------------------------------------------------------------------------
// Scratch (static __device__ arrays -- allocation-free per harness rules)
// ---------------------------------------------------------------------------
__device__ float g_qlin [MROWS * CEMB];
__device__ float g_ckv  [MROWS * RKV];
__device__ float g_kvlin[MROWS * 2 * CEMB];
__device__ float g_x1   [MROWS * CEMB];
__device__ float g_cos  [TSEQ * 32];
__device__ float g_sin  [TSEQ * 32];
// fp16 activations (GEMM A operands)
__device__ hf g_h   [MROWS * CEMB];
__device__ hf g_ckva[MROWS * RKV];
__device__ hf g_ctx [MROWS * CEMB];
__device__ hf g_h2  [MROWS * CEMB];
__device__ hf g_ff1 [MROWS * FF];
// q/k/v fp16, [B,H,T,D]
__device__ hf g_q[MROWS * CEMB];
__device__ hf g_k[MROWS * CEMB];
__device__ hf g_v[MROWS * CEMB];
// fp16 transposed weights [N,K]
__device__ hf g_wq [CEMB * CEMB];
__device__ hf g_wkvd[RKV * CEMB];
__device__ hf g_wkvu[2 * CEMB * RKV];
__device__ hf g_wpr[CEMB * CEMB];
__device__ hf g_wf1[FF * CEMB];
__device__ hf g_wf2[CEMB * FF];

// ---------------------------------------------------------------------------
// Helpers
// ---------------------------------------------------------------------------
__device__ __forceinline__ uint32_t pack2h(float x, float y)
{
    __half2 p = __floats2half2_rn(x, y);
    return *(uint32_t*)&p;
}
__device__ __forceinline__ float gelu_exact(float x)
{
    return 0.5f * x * (1.0f + erff(x * 0.70710678118654752f));
}
__device__ __forceinline__ void cpa16(uint32_t saddr, const void* g)
{
    asm volatile("cp.async.cg.shared.global [%0], [%1], 16;"
                 :: "r"(saddr), "l"(g) : "memory");
}
__device__ __forceinline__ void cpa_commit()
{
    asm volatile("cp.async.commit_group;" ::: "memory");
}
template <int N>
__device__ __forceinline__ void cpa_wait()
{
    asm volatile("cp.async.wait_group %0;" :: "n"(N) : "memory");
}
__device__ __forceinline__ void mma_f16(float& c0, float& c1, float& c2, float& c3,
                                        uint32_t a0, uint32_t a1, uint32_t a2,
                                        uint32_t a3, uint32_t b0, uint32_t b1)
{
    asm volatile(
        "mma.sync.aligned.m16n8k16.row.col.f32.f16.f16.f32 "
        "{%0,%1,%2,%3}, {%4,%5,%6,%7}, {%8,%9}, {%0,%1,%2,%3};"
        : "+f"(c0), "+f"(c1), "+f"(c2), "+f"(c3)
        : "r"(a0), "r"(a1), "r"(a2), "r"(a3), "r"(b0), "r"(b1));
}
__device__ __forceinline__ void ldm4(uint32_t& r0, uint32_t& r1, uint32_t& r2,
                                     uint32_t& r3, uint32_t a)
{
    asm volatile("ldmatrix.sync.aligned.m8n8.x4.shared.b16 {%0,%1,%2,%3}, [%4];"
                 : "=r"(r0), "=r"(r1), "=r"(r2), "=r"(r3) : "r"(a));
}
__device__ __forceinline__ void ldm4t(uint32_t& r0, uint32_t& r1, uint32_t& r2,
                                      uint32_t& r3, uint32_t a)
{
    asm volatile("ldmatrix.sync.aligned.m8n8.x4.trans.shared.b16 {%0,%1,%2,%3}, [%4];"
                 : "=r"(r0), "=r"(r1), "=r"(r2), "=r"(r3) : "r"(a));
}

// ---------------------------------------------------------------------------
// LayerNorm: writes f32 or fp16
// ---------------------------------------------------------------------------
template <bool HOUT>
__global__ void __launch_bounds__(256) ln_k(const float* __restrict__ x,
                                            const float* __restrict__ w,
                                            const float* __restrict__ b,
                                            float* __restrict__ out,
                                            hf* __restrict__ oh, int W)
{
    size_t row = blockIdx.x;
    const float* xr = x + row * (size_t)W;

    float s = 0.f, s2 = 0.f;
    for (int i = threadIdx.x << 2; i < W; i += 256 * 4) {
        float4 v = *(const float4*)(xr + i);
        s  += v.x + v.y + v.z + v.w;
        s2 += v.x * v.x + v.y * v.y + v.z * v.z + v.w * v.w;
    }
    __shared__ float sh[8][2];
    #pragma unroll
    for (int off = 16; off; off >>= 1) {
        s  += __shfl_xor_sync(0xffffffffu, s,  off);
        s2 += __shfl_xor_sync(0xffffffffu, s2, off);
    }
    int wrp = threadIdx.x >> 5, ln = threadIdx.x & 31;
    if (ln == 0) { sh[wrp][0] = s; sh[wrp][1] = s2; }
    __syncthreads();
    s = 0.f; s2 = 0.f;
    #pragma unroll
    for (int i = 0; i < 8; i++) { s += sh[i][0]; s2 += sh[i][1]; }

    float invW = 1.0f / (float)W;
    float mu   = s * invW;
    float var  = s2 * invW - mu * mu;
    float rstd = rsqrtf(var + 1e-5f);

    for (int i = threadIdx.x << 2; i < W; i += 256 * 4) {
        float4 v  = *(const float4*)(xr + i);
        float4 wv = *(const float4*)(w + i);
        float4 bv = *(const float4*)(b + i);
        float r0 = (v.x - mu) * rstd * wv.x + bv.x;
        float r1 = (v.y - mu) * rstd * wv.y + bv.y;
        float r2 = (v.z - mu) * rstd * wv.z + bv.z;
        float r3 = (v.w - mu) * rstd * wv.w + bv.w;
        if (!HOUT) {
            *(float4*)(out + row * (size_t)W + i) = make_float4(r0, r1, r2, r3);
        } else {
            *(uint32_t*)(oh + row * (size_t)W + i)     = pack2h(r0, r1);
            *(uint32_t*)(oh + row * (size_t)W + i + 2) = pack2h(r2, r3);
        }
    }
}

// ---------------------------------------------------------------------------
// Weight preprocess: W[K,N] -> T [N,K] fp16 (tiled transpose)
// ---------------------------------------------------------------------------
__global__ void __launch_bounds__(256) prep_w(const float* __restrict__ W,
                                              hf* __restrict__ T,
                                              int K, int N)
{
    __shared__ float t[32][33];
    int nb = blockIdx.x * 32, kb = blockIdx.y * 32;
    int tx = threadIdx.x & 31, ty = threadIdx.x >> 5;  // 32 x 8
    #pragma unroll
    for (int j = 0; j < 32; j += 8)
        t[ty + j][tx] = W[(size_t)(kb + ty + j) * N + nb + tx];
    __syncthreads();
    #pragma unroll
    for (int j = 0; j < 32; j += 8)
        T[(size_t)(nb + ty + j) * K + kb + tx] = __float2half_rn(t[tx][ty + j]);
}

// ---------------------------------------------------------------------------
// RoPE table + fused RoPE/transpose -> fp16 q/k/v [B,H,T,D]
// ---------------------------------------------------------------------------
__global__ void rope_tab_k(float* __restrict__ ct, float* __restrict__ st)
{
    int idx = blockIdx.x * blockDim.x + threadIdx.x;
    if (idx >= TSEQ * 32) return;
    int t = idx >> 5, d = idx & 31;
    float inv = (float)pow(10000.0, -(double)d / 32.0);
    float ang = (float)t * inv;
    ct[idx] = (float)cos((double)ang);
    st[idx] = (float)sin((double)ang);
}

__global__ void __launch_bounds__(256) rope_qkv_k(
    const float* __restrict__ qlin, const float* __restrict__ kvlin,
    const float* __restrict__ ct, const float* __restrict__ st,
    hf* __restrict__ q, hf* __restrict__ k, hf* __restrict__ v)
{
    int g = blockIdx.x * blockDim.x + threadIdx.x;
    int d = g & 31;
    int h = (g >> 5) & 15;
    int t = (g >> 9) & 2047;
    int b = g >> 20;

    float c = ct[t * 32 + d];
    float s = st[t * 32 + d];

    const float* qlp = qlin + ((size_t)(b * TSEQ + t)) * CEMB + h * HD;
    const float* klp = kvlin + ((size_t)(b * TSEQ + t)) * (2 * CEMB) + h * HD;
    const float* vlp = klp + CEMB;

    size_t o = (((size_t)(b * NH + h)) * TSEQ + t) * HD;

    float q0 = qlp[d], q1 = qlp[d + 32];
    q[o + d]      = __float2half_rn(q0 * c - q1 * s);
    q[o + d + 32] = __float2half_rn(q1 * c + q0 * s);

    float k0 = klp[d], k1 = klp[d + 32];
    k[o + d]      = __float2half_rn(k0 * c - k1 * s);
    k[o + d + 32] = __float2half_rn(k1 * c + k0 * s);

    v[o + d]      = __float2half_rn(vlp[d]);
    v[o + d + 32] = __float2half_rn(vlp[d + 32]);
}

// ---------------------------------------------------------------------------
// mma.sync fp16 GEMM (1-pass): C[M,N] = A[M,K] @ W[N,K]^T.
// BM=128, BN=256, BK=16. 8 warps (2x4), warp tile 64x64 (128 acc regs).
// LDSM bytes/MMA = 128 (was 192) -> tensor-pipe-bound, not smem-bound.
// ROWP=24 (stride-12 words, bank-conflict-free). 36KB static smem, 1 CTA/SM.
// ---------------------------------------------------------------------------
#define EPI_NONE       0
#define EPI_BIAS_RESID 1
#define EPI_BIAS_GELU  2

#define ROWP   24
#define MATB_A (128 * ROWP * 2)     // 6144
#define MATB_B (256 * ROWP * 2)     // 12288
#define STAGEB (MATB_A + MATB_B)    // 18432

template <int EPI, int HOUT>
__global__ void __launch_bounds__(256) gemm_mma(
    const hf* __restrict__ A, const hf* __restrict__ B,
    float* __restrict__ C, hf* __restrict__ Ch,
    const float* __restrict__ bias, const float* __restrict__ resid,
    int M, int N, int K)
{
    __shared__ char smem_raw[2 * STAGEB];   // 36864
    uint32_t smem_u = (uint32_t)__cvta_generic_to_shared(smem_raw);

    int tid = threadIdx.x;
    int wid = tid >> 5, lid = tid & 31;
    int wm = wid & 1, wn = wid >> 1;        // 2 x 4; warp tile 64x64
    int qr = lid >> 2, qc = lid & 3;
    int bm = blockIdx.y * 128, bn = blockIdx.x * 256;

    const hf* Ap = A + (size_t)bm * K;
    const hf* Bp = B + (size_t)bn * K;

    int NK = K >> 4;    // BK = 16

    int lrow = tid >> 1;            // 0..127
    int lc8  = (tid & 1) << 3;      // 0 or 8
    uint32_t la_off = ((uint32_t)lrow * ROWP + lc8) * 2u;

    auto stage_load = [&](int kt, int buf) {
        int k0 = kt << 4;
        uint32_t sb = smem_u + buf * STAGEB;
        // A: 256 chunks, 1 per thread
        cpa16(sb + la_off, Ap + (size_t)lrow * K + k0 + lc8);
        // B: 512 chunks, 2 per thread (rows lrow and lrow+128)
        cpa16(sb + MATB_A + la_off, Bp + (size_t)lrow * K + k0 + lc8);
        cpa16(sb + MATB_A + la_off + (uint32_t)(128 * ROWP * 2),
              Bp + (size_t)(lrow + 128) * K + k0 + lc8);
        cpa_commit();
    };

    int arow = wm * 64 + ((lid >> 3) & 1) * 8 + (lid & 7);
    int acolb = ((lid >> 4) & 1) * 8;
    int brow = wn * 64 + ((lid >> 4) & 1) * 8 + (lid & 7);
    int bcolb = ((lid >> 3) & 1) * 8;

    float acc[4][8][4] = {};

    stage_load(0, 0);

    for (int kt = 0; kt < NK; kt++) {
        int buf = kt & 1;
        if (kt + 1 < NK) {
            stage_load(kt + 1, buf ^ 1);
            cpa_wait<1>();
        } else {
            cpa_wait<0>();
        }
        __syncthreads();

        uint32_t sA = smem_u + buf * STAGEB;
        uint32_t sB = sA + MATB_A;

        uint32_t fa[4][4], fb[8][2];
        #pragma unroll
        for (int mi = 0; mi < 4; mi++)
            ldm4(fa[mi][0], fa[mi][1], fa[mi][2], fa[mi][3],
                 sA + ((uint32_t)((arow + mi * 16) * ROWP + acolb)) * 2u);
        #pragma unroll
        for (int p = 0; p < 4; p++)
            ldm4(fb[2 * p][0], fb[2 * p][1], fb[2 * p + 1][0], fb[2 * p + 1][1],
                 sB + ((uint32_t)((brow + p * 16) * ROWP + bcolb)) * 2u);
        #pragma unroll
        for (int ni = 0; ni < 8; ni++)
            #pragma unroll
            for (int mi = 0; mi < 4; mi++)
                mma_f16(acc[mi][ni][0], acc[mi][ni][1],
                        acc[mi][ni][2], acc[mi][ni][3],
                        fa[mi][0], fa[mi][1], fa[mi][2], fa[mi][3],
                        fb[ni][0], fb[ni][1]);
        __syncthreads();
    }

    #pragma unroll
    for (int mi = 0; mi < 4; mi++) {
        #pragma unroll
        for (int ni = 0; ni < 8; ni++) {
            int col = bn + wn * 64 + ni * 8 + qc * 2;
            #pragma unroll
            for (int half = 0; half < 2; half++) {
                int row = bm + wm * 64 + mi * 16 + qr + half * 8;
                size_t off = (size_t)row * N + col;
                float v0 = acc[mi][ni][half * 2 + 0];
                float v1 = acc[mi][ni][half * 2 + 1];
                if (EPI != EPI_NONE) {
                    v0 += bias[col];
                    v1 += bias[col + 1];
                }
                if (EPI == EPI_BIAS_GELU) {
                    v0 = gelu_exact(v0);
                    v1 = gelu_exact(v1);
                }
                if (EPI == EPI_BIAS_RESID) {
                    float2 rv = *(const float2*)(resid + off);
                    v0 += rv.x; v1 += rv.y;
                }
                if (!HOUT) {
                    *(float2*)(C + off) = make_float2(v0, v1);
                } else {
                    *(uint32_t*)(Ch + off) = pack2h(v0, v1);
                }
            }
        }
    }
}

// ---------------------------------------------------------------------------
// Flash attention on fp16 mma.sync (1-pass). Br=128, Bc=64, 8 warps x 16 rows.
// (unchanged from passing Round-10 kernel)
// ---------------------------------------------------------------------------
#define APAD 72
#define KVMAT (64 * APAD * 2)    // 9216 bytes per 64x64 matrix

__global__ void __launch_bounds__(256) attn_mma(
    const hf* __restrict__ q_, const hf* __restrict__ k_,
    const hf* __restrict__ v_, hf* __restrict__ ctx)
{
    __shared__ char sm[2 * KVMAT];   // 18432 bytes
    uint32_t smu = (uint32_t)__cvta_generic_to_shared(sm);

    int b = blockIdx.z, h = blockIdx.y, it = blockIdx.x;
    int t0 = it * 128;
    size_t bh = ((size_t)(b * NH + h)) * TSEQ * HD;

    int tid = threadIdx.x;
    int w = tid >> 5, lid = tid & 31;
    int qr = lid >> 2, qc = lid & 3;

    {
        const hf* src = q_ + bh + (size_t)t0 * HD;
        #pragma unroll
        for (int i = 0; i < 4; i++) {
            int chunk = tid + i * 256;
            int row = chunk >> 3, c8 = (chunk & 7) << 3;
            cpa16(smu + (row * APAD + c8) * 2, src + (size_t)row * HD + c8);
        }
        cpa_commit();
        cpa_wait<0>();
    }
    __syncthreads();

    uint32_t qa[4][4];
    {
        int row = w * 16 + ((lid >> 3) & 1) * 8 + (lid & 7);
        int colb = (lid >> 4) * 8;
        #pragma unroll
        for (int ks = 0; ks < 4; ks++) {
            uint32_t off = (uint32_t)(row * APAD + colb + ks * 16) * 2;
            ldm4(qa[ks][0], qa[ks][1], qa[ks][2], qa[ks][3], smu + off);
        }
    }

    float m_i[2] = { -1e30f, -1e30f };
    float l_i[2] = { 0.f, 0.f };
    float o[8][4] = {};
    float s[8][4];

    int nrb = ((lid >> 4) & 1) * 8 + (lid & 7);
    int ncb = ((lid >> 3) & 1) * 8;
    int srb = ((lid >> 3) & 1) * 8 + (lid & 7);
    int scb = ((lid >> 4) & 1) * 8;

    int nk = 2 * (it + 1);
    for (int kt = 0; kt < nk; kt++) {
        int k0 = kt * 64;
        __syncthreads();
        {
            const hf* srcs[2] = { k_ + bh + (size_t)k0 * HD,
                                  v_ + bh + (size_t)k0 * HD };
            #pragma unroll
            for (int i = 0; i < 4; i++) {
                int chunk = tid + i * 256;
                int mat = chunk >> 9;
                int wi = chunk & 511;
                int row = wi >> 3, c8 = (wi & 7) << 3;
                cpa16(smu + mat * KVMAT + (row * APAD + c8) * 2,
                      srcs[mat] + (size_t)row * HD + c8);
            }
            cpa_commit();
            cpa_wait<0>();
        }
        __syncthreads();

        #pragma unroll
        for (int nt = 0; nt < 8; nt++) {
            s[nt][0] = 0.f; s[nt][1] = 0.f; s[nt][2] = 0.f; s[nt][3] = 0.f;
        }
        #pragma unroll
        for (int ks = 0; ks < 4; ks++) {
            uint32_t kb[8][2];
            #pragma unroll
            for (int g = 0; g < 4; g++) {
                uint32_t a = smu + (uint32_t)((g * 16 + nrb) * APAD + ks * 16 + ncb) * 2;
                ldm4(kb[2 * g][0], kb[2 * g][1], kb[2 * g + 1][0], kb[2 * g + 1][1], a);
            }
            #pragma unroll
            for (int nt = 0; nt < 8; nt++)
                mma_f16(s[nt][0], s[nt][1], s[nt][2], s[nt][3],
                        qa[ks][0], qa[ks][1], qa[ks][2], qa[ks][3],
                        kb[nt][0], kb[nt][1]);
        }

        int row0 = t0 + w * 16 + qr;
        int row1 = row0 + 8;
        #pragma unroll
        for (int nt = 0; nt < 8; nt++) {
            int col0 = k0 + nt * 8 + qc * 2;
            s[nt][0] = (col0     > row0) ? -1e30f : s[nt][0] * 0.125f;
            s[nt][1] = (col0 + 1 > row0) ? -1e30f : s[nt][1] * 0.125f;
            s[nt][2] = (col0     > row1) ? -1e30f : s[nt][2] * 0.125f;
            s[nt][3] = (col0 + 1 > row1) ? -1e30f : s[nt][3] * 0.125f;
        }

        float mxA = -1e30f, mxB = -1e30f;
        #pragma unroll
        for (int nt = 0; nt < 8; nt++) {
            mxA = fmaxf(mxA, fmaxf(s[nt][0], s[nt][1]));
            mxB = fmaxf(mxB, fmaxf(s[nt][2], s[nt][3]));
        }
        mxA = fmaxf(mxA, __shfl_xor_sync(0xffffffffu, mxA, 1));
        mxA = fmaxf(mxA, __shfl_xor_sync(0xffffffffu, mxA, 2));
        mxB = fmaxf(mxB, __shfl_xor_sync(0xffffffffu, mxB, 1));
        mxB = fmaxf(mxB, __shfl_xor_sync(0xffffffffu, mxB, 2));

        float mnA = fmaxf(m_i[0], mxA), mnB = fmaxf(m_i[1], mxB);
        float aA = expf(m_i[0] - mnA), aB = expf(m_i[1] - mnB);
        m_i[0] = mnA; m_i[1] = mnB;

        float sumA = 0.f, sumB = 0.f;
        #pragma unroll
        for (int nt = 0; nt < 8; nt++) {
            s[nt][0] = expf(s[nt][0] - mnA); sumA += s[nt][0];
            s[nt][1] = expf(s[nt][1] - mnA); sumA += s[nt][1];
            s[nt][2] = expf(s[nt][2] - mnB); sumB += s[nt][2];
            s[nt][3] = expf(s[nt][3] - mnB); sumB += s[nt][3];
        }
        sumA += __shfl_xor_sync(0xffffffffu, sumA, 1);
        sumA += __shfl_xor_sync(0xffffffffu, sumA, 2);
        sumB += __shfl_xor_sync(0xffffffffu, sumB, 1);
        sumB += __shfl_xor_sync(0xffffffffu, sumB, 2);
        l_i[0] = l_i[0] * aA + sumA;
        l_i[1] = l_i[1] * aB + sumB;

        #pragma unroll
        for (int dt = 0; dt < 8; dt++) {
            o[dt][0] *= aA; o[dt][1] *= aA;
            o[dt][2] *= aB; o[dt][3] *= aB;
        }

        #pragma unroll
        for (int ks = 0; ks < 4; ks++) {
            uint32_t pa[4];
            pa[0] = pack2h(s[2 * ks][0],     s[2 * ks][1]);
            pa[1] = pack2h(s[2 * ks][2],     s[2 * ks][3]);
            pa[2] = pack2h(s[2 * ks + 1][0], s[2 * ks + 1][1]);
            pa[3] = pack2h(s[2 * ks + 1][2], s[2 * ks + 1][3]);

            uint32_t vb[8][2];
            #pragma unroll
            for (int g = 0; g < 4; g++) {
                uint32_t a = smu + KVMAT +
                             (uint32_t)((ks * 16 + srb) * APAD + g * 16 + scb) * 2;
                ldm4t(vb[2 * g][0], vb[2 * g][1], vb[2 * g + 1][0], vb[2 * g + 1][1], a);
            }
            #pragma unroll
            for (int dt = 0; dt < 8; dt++)
                mma_f16(o[dt][0], o[dt][1], o[dt][2], o[dt][3],
                        pa[0], pa[1], pa[2], pa[3], vb[dt][0], vb[dt][1]);
        }
    }

    float invA = 1.0f / l_i[0], invB = 1.0f / l_i[1];
    int r0 = t0 + w * 16 + qr, r1 = r0 + 8;
    #pragma unroll
    for (int dt = 0; dt < 8; dt++) {
        int col = h * HD + dt * 8 + qc * 2;
        size_t off0 = ((size_t)(b * TSEQ + r0)) * CEMB + col;
        *(uint32_t*)(ctx + off0) = pack2h(o[dt][0] * invA, o[dt][1] * invA);
        size_t off1 = ((size_t)(b * TSEQ + r1)) * CEMB + col;
        *(uint32_t*)(ctx + off1) = pack2h(o[dt][2] * invB, o[dt][3] * invB);
    }
}

// ---------------------------------------------------------------------------
// Launch (indices 3 AND 5 are main GEMMs for ncu capture)
// ---------------------------------------------------------------------------
static float* sym(const void* s)
{
    void* p = nullptr;
    cudaGetSymbolAddress(&p, s);
    return (float*)p;
}
static hf* symh(const void* s)
{
    void* p = nullptr;
    cudaGetSymbolAddress(&p, s);
    return (hf*)p;
}

extern "C" void kernel_launch(void* const* d_in, const int* in_sizes, int n_in,
                              void* d_out, int out_size)
{
    const float* x      = (const float*)d_in[0];
    const float* ln1_w  = (const float*)d_in[1];
    const float* ln1_b  = (const float*)d_in[2];
    const float* ln2_w  = (const float*)d_in[3];
    const float* ln2_b  = (const float*)d_in[4];
    const float* q_w    = (const float*)d_in[5];
    const float* kvd_w  = (const float*)d_in[6];
    const float* kvln_w = (const float*)d_in[7];
    const float* kvln_b = (const float*)d_in[8];
    const float* kvu_w  = (const float*)d_in[9];
    const float* proj_w = (const float*)d_in[10];
    const float* proj_b = (const float*)d_in[11];
    const float* f1_w   = (const float*)d_in[12];
    const float* f1_b   = (const float*)d_in[13];
    const float* f2_w   = (const float*)d_in[14];
    const float* f2_b   = (const float*)d_in[15];
    float* out = (float*)d_out;

    float* qlin  = sym(g_qlin);
    float* ckv   = sym(g_ckv);
    float* kvlin = sym(g_kvlin);
    float* x1    = sym(g_x1);
    float* ct    = sym(g_cos);
    float* st    = sym(g_sin);
    hf *hh  = symh(g_h);
    hf *cva = symh(g_ckva);
    hf *ctx = symh(g_ctx);
    hf *h2  = symh(g_h2);
    hf *ff1 = symh(g_ff1);
    hf *q = symh(g_q), *k = symh(g_k), *v = symh(g_v);
    hf *wq = symh(g_wq), *wd = symh(g_wkvd), *wu = symh(g_wkvu);
    hf *wp = symh(g_wpr), *w1 = symh(g_wf1), *w2 = symh(g_wf2);

    // 0: prep q_w
    prep_w<<<dim3(CEMB / 32, CEMB / 32), 256>>>(q_w, wq, CEMB, CEMB);
    // 1: h = LN1(x) -> fp16
    ln_k<true><<<MROWS, 256>>>(x, ln1_w, ln1_b, nullptr, hh, CEMB);
    // 2: prep kvd_w
    prep_w<<<dim3(RKV / 32, CEMB / 32), 256>>>(kvd_w, wd, CEMB, RKV);
    // 3: qlin = h @ q_w            <-- ncu target (offset 2)
    gemm_mma<EPI_NONE, 0><<<dim3(CEMB / 256, MROWS / 128), 256>>>(
        hh, wq, qlin, nullptr, nullptr, nullptr, MROWS, CEMB, CEMB);
    // 4: prep kvu_w
    prep_w<<<dim3(2 * CEMB / 32, RKV / 32), 256>>>(kvu_w, wu, RKV, 2 * CEMB);
    // 5: ckv = h @ kvd_w           <-- ncu target (offset 0)
    gemm_mma<EPI_NONE, 0><<<dim3(RKV / 256, MROWS / 128), 256>>>(
        hh, wd, ckv, nullptr, nullptr, nullptr, MROWS, RKV, CEMB);
    // 6: ckv = LN_kv(ckv) -> fp16
    ln_k<true><<<MROWS, 256>>>(ckv, kvln_w, kvln_b, nullptr, cva, RKV);
    // 7: kvlin = ckv @ kvu_w
    gemm_mma<EPI_NONE, 0><<<dim3(2 * CEMB / 256, MROWS / 128), 256>>>(
        cva, wu, kvlin, nullptr, nullptr, nullptr, MROWS, 2 * CEMB, RKV);
    // 8: prep proj_w
    prep_w<<<dim3(CEMB / 32, CEMB / 32), 256>>>(proj_w, wp, CEMB, CEMB);
    // 9/10: rope
    rope_tab_k<<<(TSEQ * 32 + 255) / 256, 256>>>(ct, st);
    rope_qkv_k<<<(BSZ * TSEQ * NH * 32) / 256, 256>>>(qlin, kvlin, ct, st, q, k, v);
    // 11: flash attention
    attn_mma<<<dim3(TSEQ / 128, NH, BSZ), 256>>>(q, k, v, ctx);
    // 12: x1 = x + ctx @ proj_w + proj_b
    gemm_mma<EPI_BIAS_RESID, 0><<<dim3(CEMB / 256, MROWS / 128), 256>>>(
        ctx, wp, x1, nullptr, proj_b, x, MROWS, CEMB, CEMB);
    // 13: h2 = LN2(x1) -> fp16
    ln_k<true><<<MROWS, 256>>>(x1, ln2_w, ln2_b, nullptr, h2, CEMB);
    // 14: prep f1_w
    prep_w<<<dim3(FF / 32, CEMB / 32), 256>>>(f1_w, w1, CEMB, FF);
    // 15: ff1 = gelu(h2 @ f1_w + f1_b) -> fp16
    gemm_mma<EPI_BIAS_GELU, 1><<<dim3(FF / 256, MROWS / 128), 256>>>(
        h2, w1, nullptr, ff1, f1_b, nullptr, MROWS, FF, CEMB);
    // 16: prep f2_w
    prep_w<<<dim3(CEMB / 32, FF / 32), 256>>>(f2_w, w2, FF, CEMB);
    // 17: out = x1 + ff1 @ f2_w + f2_b
    gemm_mma<EPI_BIAS_RESID, 0><<<dim3(CEMB / 256, MROWS / 128), 256>>>(
        ff1, w2, out, nullptr, f2_b, x1, MROWS, CEMB, FF);
}

// round 12
// speedup vs baseline: 1.2478x; 1.2478x over previous
#include <cuda_runtime.h>
#include <cuda_fp16.h>
#include <math.h>
#include <stdint.h>

// ---------------------------------------------------------------------------
// Problem constants
// ---------------------------------------------------------------------------
#define BSZ   4
#define TSEQ  2048
#define CEMB  1024
#define NH    16
#define HD    64
#define RKV   512
#define FF    4096
#define MROWS (BSZ * TSEQ)   // 8192

typedef __half hf;

// ---------------------------------------------------------------------------
// Scratch (static __device__ arrays -- allocation-free per harness rules)
// ---------------------------------------------------------------------------
__device__ float g_ckv  [MROWS * RKV];
__device__ float g_x1   [MROWS * CEMB];
__device__ float g_cos  [TSEQ * 32];
__device__ float g_sin  [TSEQ * 32];
// fp16 intermediates
__device__ hf g_qlin [MROWS * CEMB];
__device__ hf g_kvlin[MROWS * 2 * CEMB];
// fp16 activations (GEMM A operands)
__device__ hf g_h   [MROWS * CEMB];
__device__ hf g_ckva[MROWS * RKV];
__device__ hf g_ctx [MROWS * CEMB];
__device__ hf g_h2  [MROWS * CEMB];
__device__ hf g_ff1 [MROWS * FF];
// q/k/v fp16, [B,H,T,D]
__device__ hf g_q[MROWS * CEMB];
__device__ hf g_k[MROWS * CEMB];
__device__ hf g_v[MROWS * CEMB];
// fp16 transposed weights [N,K]
__device__ hf g_wq [CEMB * CEMB];
__device__ hf g_wkvd[RKV * CEMB];
__device__ hf g_wkvu[2 * CEMB * RKV];
__device__ hf g_wpr[CEMB * CEMB];
__device__ hf g_wf1[FF * CEMB];
__device__ hf g_wf2[CEMB * FF];

// ---------------------------------------------------------------------------
// Helpers
// ---------------------------------------------------------------------------
__device__ __forceinline__ uint32_t pack2h(float x, float y)
{
    __half2 p = __floats2half2_rn(x, y);
    return *(uint32_t*)&p;
}
__device__ __forceinline__ float gelu_exact(float x)
{
    return 0.5f * x * (1.0f + erff(x * 0.70710678118654752f));
}
__device__ __forceinline__ void cpa16(uint32_t saddr, const void* g)
{
    asm volatile("cp.async.cg.shared.global [%0], [%1], 16;"
                 :: "r"(saddr), "l"(g) : "memory");
}
__device__ __forceinline__ void cpa_commit()
{
    asm volatile("cp.async.commit_group;" ::: "memory");
}
template <int N>
__device__ __forceinline__ void cpa_wait()
{
    asm volatile("cp.async.wait_group %0;" :: "n"(N) : "memory");
}
__device__ __forceinline__ void mma_f16(float& c0, float& c1, float& c2, float& c3,
                                        uint32_t a0, uint32_t a1, uint32_t a2,
                                        uint32_t a3, uint32_t b0, uint32_t b1)
{
    asm volatile(
        "mma.sync.aligned.m16n8k16.row.col.f32.f16.f16.f32 "
        "{%0,%1,%2,%3}, {%4,%5,%6,%7}, {%8,%9}, {%0,%1,%2,%3};"
        : "+f"(c0), "+f"(c1), "+f"(c2), "+f"(c3)
        : "r"(a0), "r"(a1), "r"(a2), "r"(a3), "r"(b0), "r"(b1));
}
__device__ __forceinline__ void ldm4(uint32_t& r0, uint32_t& r1, uint32_t& r2,
                                     uint32_t& r3, uint32_t a)
{
    asm volatile("ldmatrix.sync.aligned.m8n8.x4.shared.b16 {%0,%1,%2,%3}, [%4];"
                 : "=r"(r0), "=r"(r1), "=r"(r2), "=r"(r3) : "r"(a));
}
__device__ __forceinline__ void ldm4t(uint32_t& r0, uint32_t& r1, uint32_t& r2,
                                      uint32_t& r3, uint32_t a)
{
    asm volatile("ldmatrix.sync.aligned.m8n8.x4.trans.shared.b16 {%0,%1,%2,%3}, [%4];"
                 : "=r"(r0), "=r"(r1), "=r"(r2), "=r"(r3) : "r"(a));
}

// ---------------------------------------------------------------------------
// LayerNorm: writes f32 or fp16
// ---------------------------------------------------------------------------
template <bool HOUT>
__global__ void __launch_bounds__(256) ln_k(const float* __restrict__ x,
                                            const float* __restrict__ w,
                                            const float* __restrict__ b,
                                            float* __restrict__ out,
                                            hf* __restrict__ oh, int W)
{
    size_t row = blockIdx.x;
    const float* xr = x + row * (size_t)W;

    float s = 0.f, s2 = 0.f;
    for (int i = threadIdx.x << 2; i < W; i += 256 * 4) {
        float4 v = *(const float4*)(xr + i);
        s  += v.x + v.y + v.z + v.w;
        s2 += v.x * v.x + v.y * v.y + v.z * v.z + v.w * v.w;
    }
    __shared__ float sh[8][2];
    #pragma unroll
    for (int off = 16; off; off >>= 1) {
        s  += __shfl_xor_sync(0xffffffffu, s,  off);
        s2 += __shfl_xor_sync(0xffffffffu, s2, off);
    }
    int wrp = threadIdx.x >> 5, ln = threadIdx.x & 31;
    if (ln == 0) { sh[wrp][0] = s; sh[wrp][1] = s2; }
    __syncthreads();
    s = 0.f; s2 = 0.f;
    #pragma unroll
    for (int i = 0; i < 8; i++) { s += sh[i][0]; s2 += sh[i][1]; }

    float invW = 1.0f / (float)W;
    float mu   = s * invW;
    float var  = s2 * invW - mu * mu;
    float rstd = rsqrtf(var + 1e-5f);

    for (int i = threadIdx.x << 2; i < W; i += 256 * 4) {
        float4 v  = *(const float4*)(xr + i);
        float4 wv = *(const float4*)(w + i);
        float4 bv = *(const float4*)(b + i);
        float r0 = (v.x - mu) * rstd * wv.x + bv.x;
        float r1 = (v.y - mu) * rstd * wv.y + bv.y;
        float r2 = (v.z - mu) * rstd * wv.z + bv.z;
        float r3 = (v.w - mu) * rstd * wv.w + bv.w;
        if (!HOUT) {
            *(float4*)(out + row * (size_t)W + i) = make_float4(r0, r1, r2, r3);
        } else {
            *(uint32_t*)(oh + row * (size_t)W + i)     = pack2h(r0, r1);
            *(uint32_t*)(oh + row * (size_t)W + i + 2) = pack2h(r2, r3);
        }
    }
}

// ---------------------------------------------------------------------------
// Weight preprocess: W[K,N] -> T [N,K] fp16 (tiled transpose)
// ---------------------------------------------------------------------------
__global__ void __launch_bounds__(256) prep_w(const float* __restrict__ W,
                                              hf* __restrict__ T,
                                              int K, int N)
{
    __shared__ float t[32][33];
    int nb = blockIdx.x * 32, kb = blockIdx.y * 32;
    int tx = threadIdx.x & 31, ty = threadIdx.x >> 5;  // 32 x 8
    #pragma unroll
    for (int j = 0; j < 32; j += 8)
        t[ty + j][tx] = W[(size_t)(kb + ty + j) * N + nb + tx];
    __syncthreads();
    #pragma unroll
    for (int j = 0; j < 32; j += 8)
        T[(size_t)(nb + ty + j) * K + kb + tx] = __float2half_rn(t[tx][ty + j]);
}

// ---------------------------------------------------------------------------
// RoPE table + fused RoPE/transpose (fp16 in) -> fp16 q/k/v [B,H,T,D]
// ---------------------------------------------------------------------------
__global__ void rope_tab_k(float* __restrict__ ct, float* __restrict__ st)
{
    int idx = blockIdx.x * blockDim.x + threadIdx.x;
    if (idx >= TSEQ * 32) return;
    int t = idx >> 5, d = idx & 31;
    float inv = (float)pow(10000.0, -(double)d / 32.0);
    float ang = (float)t * inv;
    ct[idx] = (float)cos((double)ang);
    st[idx] = (float)sin((double)ang);
}

__global__ void __launch_bounds__(256) rope_qkv_k(
    const hf* __restrict__ qlin, const hf* __restrict__ kvlin,
    const float* __restrict__ ct, const float* __restrict__ st,
    hf* __restrict__ q, hf* __restrict__ k, hf* __restrict__ v)
{
    int g = blockIdx.x * blockDim.x + threadIdx.x;
    int d = g & 31;
    int h = (g >> 5) & 15;
    int t = (g >> 9) & 2047;
    int b = g >> 20;

    float c = ct[t * 32 + d];
    float s = st[t * 32 + d];

    const hf* qlp = qlin + ((size_t)(b * TSEQ + t)) * CEMB + h * HD;
    const hf* klp = kvlin + ((size_t)(b * TSEQ + t)) * (2 * CEMB) + h * HD;
    const hf* vlp = klp + CEMB;

    size_t o = (((size_t)(b * NH + h)) * TSEQ + t) * HD;

    float q0 = __half2float(qlp[d]), q1 = __half2float(qlp[d + 32]);
    q[o + d]      = __float2half_rn(q0 * c - q1 * s);
    q[o + d + 32] = __float2half_rn(q1 * c + q0 * s);

    float k0 = __half2float(klp[d]), k1 = __half2float(klp[d + 32]);
    k[o + d]      = __float2half_rn(k0 * c - k1 * s);
    k[o + d + 32] = __float2half_rn(k1 * c + k0 * s);

    v[o + d]      = vlp[d];
    v[o + d + 32] = vlp[d + 32];
}

// ---------------------------------------------------------------------------
// mma.sync fp16 GEMM (1-pass, persistent grid): C[M,N] = A[M,K] @ W[N,K]^T.
// BM=BN=128, BK=32, 8 warps (2x4), warp tile 64x32. ROWP=40 (conflict-free).
// 2-stage cp.async, 40KB static smem, 2 CTAs/SM. Grid = 296 fixed; each CTA
// loops over output tiles -> no wave-quantization tails.
// ---------------------------------------------------------------------------
#define EPI_NONE       0
#define EPI_BIAS_RESID 1
#define EPI_BIAS_GELU  2

#define ROWP   40
#define MATB   (128 * ROWP * 2)     // 10240 bytes
#define STAGEB (2 * MATB)           // A, B
#define GEMM_GRID 296

template <int EPI, int HOUT>
__global__ void __launch_bounds__(256, 2) gemm_mma(
    const hf* __restrict__ A, const hf* __restrict__ B,
    float* __restrict__ C, hf* __restrict__ Ch,
    const float* __restrict__ bias, const float* __restrict__ resid,
    int M, int N, int K)
{
    __shared__ char smem_raw[2 * STAGEB];   // 40960
    uint32_t smem_u = (uint32_t)__cvta_generic_to_shared(smem_raw);

    int tid = threadIdx.x;
    int wid = tid >> 5, lid = tid & 31;
    int wm = wid & 1, wn = wid >> 1;
    int qr = lid >> 2, qc = lid & 3;

    int NK = K >> 5;    // BK = 32
    int ntx = N >> 7;
    int tiles = (M >> 7) * ntx;

    int lrow = tid >> 2;            // 0..63 base rows (2 chunks/thread)
    int lc8  = (tid & 3) << 3;      // 0,8,16,24

    int arow = wm * 64 + ((lid >> 3) & 1) * 8 + (lid & 7);
    int acolb = ((lid >> 4) & 1) * 8;
    int brow = wn * 32 + ((lid >> 4) & 1) * 8 + (lid & 7);
    int bcolb = ((lid >> 3) & 1) * 8;

    for (int tile = blockIdx.x; tile < tiles; tile += GEMM_GRID) {
        int bm = (tile / ntx) << 7;
        int bn = (tile % ntx) << 7;

        const hf* Ap = A + (size_t)bm * K;
        const hf* Bp = B + (size_t)bn * K;

        auto stage_load = [&](int kt, int buf) {
            #pragma unroll
            for (int i = 0; i < 2; i++) {
                int row = lrow + i * 64;
                size_t go = (size_t)row * K + (kt << 5) + lc8;
                uint32_t sa = smem_u + buf * STAGEB +
                              ((uint32_t)row * ROWP + lc8) * 2u;
                cpa16(sa + 0 * MATB, Ap + go);
                cpa16(sa + 1 * MATB, Bp + go);
            }
            cpa_commit();
        };

        float acc[4][4][4] = {};

        stage_load(0, 0);

        for (int kt = 0; kt < NK; kt++) {
            int buf = kt & 1;
            if (kt + 1 < NK) {
                stage_load(kt + 1, buf ^ 1);
                cpa_wait<1>();
            } else {
                cpa_wait<0>();
            }
            __syncthreads();

            uint32_t sA = smem_u + buf * STAGEB + 0 * MATB;
            uint32_t sB = smem_u + buf * STAGEB + 1 * MATB;

            #pragma unroll
            for (int kh = 0; kh < 2; kh++) {
                int kc = kh * 16;
                uint32_t fa[4][4], fb[4][2];
                #pragma unroll
                for (int mi = 0; mi < 4; mi++)
                    ldm4(fa[mi][0], fa[mi][1], fa[mi][2], fa[mi][3],
                         sA + ((uint32_t)((arow + mi * 16) * ROWP + kc + acolb)) * 2u);
                #pragma unroll
                for (int p = 0; p < 2; p++)
                    ldm4(fb[2 * p][0], fb[2 * p][1],
                         fb[2 * p + 1][0], fb[2 * p + 1][1],
                         sB + ((uint32_t)((brow + p * 16) * ROWP + kc + bcolb)) * 2u);
                #pragma unroll
                for (int ni = 0; ni < 4; ni++)
                    #pragma unroll
                    for (int mi = 0; mi < 4; mi++)
                        mma_f16(acc[mi][ni][0], acc[mi][ni][1],
                                acc[mi][ni][2], acc[mi][ni][3],
                                fa[mi][0], fa[mi][1], fa[mi][2], fa[mi][3],
                                fb[ni][0], fb[ni][1]);
            }
            __syncthreads();
        }

        #pragma unroll
        for (int mi = 0; mi < 4; mi++) {
            #pragma unroll
            for (int ni = 0; ni < 4; ni++) {
                int col = bn + wn * 32 + ni * 8 + qc * 2;
                #pragma unroll
                for (int half = 0; half < 2; half++) {
                    int row = bm + wm * 64 + mi * 16 + qr + half * 8;
                    size_t off = (size_t)row * N + col;
                    float v0 = acc[mi][ni][half * 2 + 0];
                    float v1 = acc[mi][ni][half * 2 + 1];
                    if (EPI != EPI_NONE) {
                        v0 += bias[col];
                        v1 += bias[col + 1];
                    }
                    if (EPI == EPI_BIAS_GELU) {
                        v0 = gelu_exact(v0);
                        v1 = gelu_exact(v1);
                    }
                    if (EPI == EPI_BIAS_RESID) {
                        float2 rv = *(const float2*)(resid + off);
                        v0 += rv.x; v1 += rv.y;
                    }
                    if (!HOUT) {
                        *(float2*)(C + off) = make_float2(v0, v1);
                    } else {
                        *(uint32_t*)(Ch + off) = pack2h(v0, v1);
                    }
                }
            }
        }
    }
}

// ---------------------------------------------------------------------------
// Flash attention on fp16 mma.sync (1-pass). Br=128, Bc=64, 8 warps x 16 rows.
// (unchanged from passing Round-10 kernel)
// ---------------------------------------------------------------------------
#define APAD 72
#define KVMAT (64 * APAD * 2)    // 9216 bytes per 64x64 matrix

__global__ void __launch_bounds__(256) attn_mma(
    const hf* __restrict__ q_, const hf* __restrict__ k_,
    const hf* __restrict__ v_, hf* __restrict__ ctx)
{
    __shared__ char sm[2 * KVMAT];   // 18432 bytes
    uint32_t smu = (uint32_t)__cvta_generic_to_shared(sm);

    int b = blockIdx.z, h = blockIdx.y, it = blockIdx.x;
    int t0 = it * 128;
    size_t bh = ((size_t)(b * NH + h)) * TSEQ * HD;

    int tid = threadIdx.x;
    int w = tid >> 5, lid = tid & 31;
    int qr = lid >> 2, qc = lid & 3;

    {
        const hf* src = q_ + bh + (size_t)t0 * HD;
        #pragma unroll
        for (int i = 0; i < 4; i++) {
            int chunk = tid + i * 256;
            int row = chunk >> 3, c8 = (chunk & 7) << 3;
            cpa16(smu + (row * APAD + c8) * 2, src + (size_t)row * HD + c8);
        }
        cpa_commit();
        cpa_wait<0>();
    }
    __syncthreads();

    uint32_t qa[4][4];
    {
        int row = w * 16 + ((lid >> 3) & 1) * 8 + (lid & 7);
        int colb = (lid >> 4) * 8;
        #pragma unroll
        for (int ks = 0; ks < 4; ks++) {
            uint32_t off = (uint32_t)(row * APAD + colb + ks * 16) * 2;
            ldm4(qa[ks][0], qa[ks][1], qa[ks][2], qa[ks][3], smu + off);
        }
    }

    float m_i[2] = { -1e30f, -1e30f };
    float l_i[2] = { 0.f, 0.f };
    float o[8][4] = {};
    float s[8][4];

    int nrb = ((lid >> 4) & 1) * 8 + (lid & 7);
    int ncb = ((lid >> 3) & 1) * 8;
    int srb = ((lid >> 3) & 1) * 8 + (lid & 7);
    int scb = ((lid >> 4) & 1) * 8;

    int nk = 2 * (it + 1);
    for (int kt = 0; kt < nk; kt++) {
        int k0 = kt * 64;
        __syncthreads();
        {
            const hf* srcs[2] = { k_ + bh + (size_t)k0 * HD,
                                  v_ + bh + (size_t)k0 * HD };
            #pragma unroll
            for (int i = 0; i < 4; i++) {
                int chunk = tid + i * 256;
                int mat = chunk >> 9;
                int wi = chunk & 511;
                int row = wi >> 3, c8 = (wi & 7) << 3;
                cpa16(smu + mat * KVMAT + (row * APAD + c8) * 2,
                      srcs[mat] + (size_t)row * HD + c8);
            }
            cpa_commit();
            cpa_wait<0>();
        }
        __syncthreads();

        #pragma unroll
        for (int nt = 0; nt < 8; nt++) {
            s[nt][0] = 0.f; s[nt][1] = 0.f; s[nt][2] = 0.f; s[nt][3] = 0.f;
        }
        #pragma unroll
        for (int ks = 0; ks < 4; ks++) {
            uint32_t kb[8][2];
            #pragma unroll
            for (int g = 0; g < 4; g++) {
                uint32_t a = smu + (uint32_t)((g * 16 + nrb) * APAD + ks * 16 + ncb) * 2;
                ldm4(kb[2 * g][0], kb[2 * g][1], kb[2 * g + 1][0], kb[2 * g + 1][1], a);
            }
            #pragma unroll
            for (int nt = 0; nt < 8; nt++)
                mma_f16(s[nt][0], s[nt][1], s[nt][2], s[nt][3],
                        qa[ks][0], qa[ks][1], qa[ks][2], qa[ks][3],
                        kb[nt][0], kb[nt][1]);
        }

        int row0 = t0 + w * 16 + qr;
        int row1 = row0 + 8;
        #pragma unroll
        for (int nt = 0; nt < 8; nt++) {
            int col0 = k0 + nt * 8 + qc * 2;
            s[nt][0] = (col0     > row0) ? -1e30f : s[nt][0] * 0.125f;
            s[nt][1] = (col0 + 1 > row0) ? -1e30f : s[nt][1] * 0.125f;
            s[nt][2] = (col0     > row1) ? -1e30f : s[nt][2] * 0.125f;
            s[nt][3] = (col0 + 1 > row1) ? -1e30f : s[nt][3] * 0.125f;
        }

        float mxA = -1e30f, mxB = -1e30f;
        #pragma unroll
        for (int nt = 0; nt < 8; nt++) {
            mxA = fmaxf(mxA, fmaxf(s[nt][0], s[nt][1]));
            mxB = fmaxf(mxB, fmaxf(s[nt][2], s[nt][3]));
        }
        mxA = fmaxf(mxA, __shfl_xor_sync(0xffffffffu, mxA, 1));
        mxA = fmaxf(mxA, __shfl_xor_sync(0xffffffffu, mxA, 2));
        mxB = fmaxf(mxB, __shfl_xor_sync(0xffffffffu, mxB, 1));
        mxB = fmaxf(mxB, __shfl_xor_sync(0xffffffffu, mxB, 2));

        float mnA = fmaxf(m_i[0], mxA), mnB = fmaxf(m_i[1], mxB);
        float aA = expf(m_i[0] - mnA), aB = expf(m_i[1] - mnB);
        m_i[0] = mnA; m_i[1] = mnB;

        float sumA = 0.f, sumB = 0.f;
        #pragma unroll
        for (int nt = 0; nt < 8; nt++) {
            s[nt][0] = expf(s[nt][0] - mnA); sumA += s[nt][0];
            s[nt][1] = expf(s[nt][1] - mnA); sumA += s[nt][1];
            s[nt][2] = expf(s[nt][2] - mnB); sumB += s[nt][2];
            s[nt][3] = expf(s[nt][3] - mnB); sumB += s[nt][3];
        }
        sumA += __shfl_xor_sync(0xffffffffu, sumA, 1);
        sumA += __shfl_xor_sync(0xffffffffu, sumA, 2);
        sumB += __shfl_xor_sync(0xffffffffu, sumB, 1);
        sumB += __shfl_xor_sync(0xffffffffu, sumB, 2);
        l_i[0] = l_i[0] * aA + sumA;
        l_i[1] = l_i[1] * aB + sumB;

        #pragma unroll
        for (int dt = 0; dt < 8; dt++) {
            o[dt][0] *= aA; o[dt][1] *= aA;
            o[dt][2] *= aB; o[dt][3] *= aB;
        }

        #pragma unroll
        for (int ks = 0; ks < 4; ks++) {
            uint32_t pa[4];
            pa[0] = pack2h(s[2 * ks][0],     s[2 * ks][1]);
            pa[1] = pack2h(s[2 * ks][2],     s[2 * ks][3]);
            pa[2] = pack2h(s[2 * ks + 1][0], s[2 * ks + 1][1]);
            pa[3] = pack2h(s[2 * ks + 1][2], s[2 * ks + 1][3]);

            uint32_t vb[8][2];
            #pragma unroll
            for (int g = 0; g < 4; g++) {
                uint32_t a = smu + KVMAT +
                             (uint32_t)((ks * 16 + srb) * APAD + g * 16 + scb) * 2;
                ldm4t(vb[2 * g][0], vb[2 * g][1], vb[2 * g + 1][0], vb[2 * g + 1][1], a);
            }
            #pragma unroll
            for (int dt = 0; dt < 8; dt++)
                mma_f16(o[dt][0], o[dt][1], o[dt][2], o[dt][3],
                        pa[0], pa[1], pa[2], pa[3], vb[dt][0], vb[dt][1]);
        }
    }

    float invA = 1.0f / l_i[0], invB = 1.0f / l_i[1];
    int r0 = t0 + w * 16 + qr, r1 = r0 + 8;
    #pragma unroll
    for (int dt = 0; dt < 8; dt++) {
        int col = h * HD + dt * 8 + qc * 2;
        size_t off0 = ((size_t)(b * TSEQ + r0)) * CEMB + col;
        *(uint32_t*)(ctx + off0) = pack2h(o[dt][0] * invA, o[dt][1] * invA);
        size_t off1 = ((size_t)(b * TSEQ + r1)) * CEMB + col;
        *(uint32_t*)(ctx + off1) = pack2h(o[dt][2] * invB, o[dt][3] * invB);
    }
}

// ---------------------------------------------------------------------------
// Launch (indices 3 AND 5 are main GEMMs for ncu capture)
// ---------------------------------------------------------------------------
static float* sym(const void* s)
{
    void* p = nullptr;
    cudaGetSymbolAddress(&p, s);
    return (float*)p;
}
static hf* symh(const void* s)
{
    void* p = nullptr;
    cudaGetSymbolAddress(&p, s);
    return (hf*)p;
}

extern "C" void kernel_launch(void* const* d_in, const int* in_sizes, int n_in,
                              void* d_out, int out_size)
{
    const float* x      = (const float*)d_in[0];
    const float* ln1_w  = (const float*)d_in[1];
    const float* ln1_b  = (const float*)d_in[2];
    const float* ln2_w  = (const float*)d_in[3];
    const float* ln2_b  = (const float*)d_in[4];
    const float* q_w    = (const float*)d_in[5];
    const float* kvd_w  = (const float*)d_in[6];
    const float* kvln_w = (const float*)d_in[7];
    const float* kvln_b = (const float*)d_in[8];
    const float* kvu_w  = (const float*)d_in[9];
    const float* proj_w = (const float*)d_in[10];
    const float* proj_b = (const float*)d_in[11];
    const float* f1_w   = (const float*)d_in[12];
    const float* f1_b   = (const float*)d_in[13];
    const float* f2_w   = (const float*)d_in[14];
    const float* f2_b   = (const float*)d_in[15];
    float* out = (float*)d_out;

    float* ckv   = sym(g_ckv);
    float* x1    = sym(g_x1);
    float* ct    = sym(g_cos);
    float* st    = sym(g_sin);
    hf *qlin  = symh(g_qlin);
    hf *kvlin = symh(g_kvlin);
    hf *hh  = symh(g_h);
    hf *cva = symh(g_ckva);
    hf *ctx = symh(g_ctx);
    hf *h2  = symh(g_h2);
    hf *ff1 = symh(g_ff1);
    hf *q = symh(g_q), *k = symh(g_k), *v = symh(g_v);
    hf *wq = symh(g_wq), *wd = symh(g_wkvd), *wu = symh(g_wkvu);
    hf *wp = symh(g_wpr), *w1 = symh(g_wf1), *w2 = symh(g_wf2);

    // 0: prep q_w
    prep_w<<<dim3(CEMB / 32, CEMB / 32), 256>>>(q_w, wq, CEMB, CEMB);
    // 1: h = LN1(x) -> fp16
    ln_k<true><<<MROWS, 256>>>(x, ln1_w, ln1_b, nullptr, hh, CEMB);
    // 2: prep kvd_w
    prep_w<<<dim3(RKV / 32, CEMB / 32), 256>>>(kvd_w, wd, CEMB, RKV);
    // 3: qlin = h @ q_w -> fp16      <-- ncu target (offset 2)
    gemm_mma<EPI_NONE, 1><<<GEMM_GRID, 256>>>(
        hh, wq, nullptr, qlin, nullptr, nullptr, MROWS, CEMB, CEMB);
    // 4: prep kvu_w
    prep_w<<<dim3(2 * CEMB / 32, RKV / 32), 256>>>(kvu_w, wu, RKV, 2 * CEMB);
    // 5: ckv = h @ kvd_w (f32)       <-- ncu target (offset 0)
    gemm_mma<EPI_NONE, 0><<<GEMM_GRID, 256>>>(
        hh, wd, ckv, nullptr, nullptr, nullptr, MROWS, RKV, CEMB);
    // 6: ckv = LN_kv(ckv) -> fp16
    ln_k<true><<<MROWS, 256>>>(ckv, kvln_w, kvln_b, nullptr, cva, RKV);
    // 7: kvlin = ckv @ kvu_w -> fp16
    gemm_mma<EPI_NONE, 1><<<GEMM_GRID, 256>>>(
        cva, wu, nullptr, kvlin, nullptr, nullptr, MROWS, 2 * CEMB, RKV);
    // 8: prep proj_w
    prep_w<<<dim3(CEMB / 32, CEMB / 32), 256>>>(proj_w, wp, CEMB, CEMB);
    // 9/10: rope
    rope_tab_k<<<(TSEQ * 32 + 255) / 256, 256>>>(ct, st);
    rope_qkv_k<<<(BSZ * TSEQ * NH * 32) / 256, 256>>>(qlin, kvlin, ct, st, q, k, v);
    // 11: flash attention
    attn_mma<<<dim3(TSEQ / 128, NH, BSZ), 256>>>(q, k, v, ctx);
    // 12: x1 = x + ctx @ proj_w + proj_b (f32)
    gemm_mma<EPI_BIAS_RESID, 0><<<GEMM_GRID, 256>>>(
        ctx, wp, x1, nullptr, proj_b, x, MROWS, CEMB, CEMB);
    // 13: h2 = LN2(x1) -> fp16
    ln_k<true><<<MROWS, 256>>>(x1, ln2_w, ln2_b, nullptr, h2, CEMB);
    // 14: prep f1_w
    prep_w<<<dim3(FF / 32, CEMB / 32), 256>>>(f1_w, w1, CEMB, FF);
    // 15: ff1 = gelu(h2 @ f1_w + f1_b) -> fp16
    gemm_mma<EPI_BIAS_GELU, 1><<<GEMM_GRID, 256>>>(
        h2, w1, nullptr, ff1, f1_b, nullptr, MROWS, FF, CEMB);
    // 16: prep f2_w
    prep_w<<<dim3(CEMB / 32, FF / 32), 256>>>(f2_w, w2, FF, CEMB);
    // 17: out = x1 + ff1 @ f2_w + f2_b (f32)
    gemm_mma<EPI_BIAS_RESID, 0><<<GEMM_GRID, 256>>>(
        ff1, w2, out, nullptr, f2_b, x1, MROWS, CEMB, FF);
}

// round 14
// speedup vs baseline: 1.3423x; 1.0757x over previous
#include <cuda_runtime.h>
#include <cuda_fp16.h>
#include <math.h>
#include <stdint.h>

// ---------------------------------------------------------------------------
// Problem constants
// ---------------------------------------------------------------------------
#define BSZ   4
#define TSEQ  2048
#define CEMB  1024
#define NH    16
#define HD    64
#define RKV   512
#define FF    4096
#define MROWS (BSZ * TSEQ)   // 8192

typedef __half hf;

// ---------------------------------------------------------------------------
// Scratch (static __device__ arrays -- allocation-free per harness rules)
// ---------------------------------------------------------------------------
__device__ float g_ckv  [MROWS * RKV];
__device__ float g_x1   [MROWS * CEMB];
__device__ float g_cos  [TSEQ * 32];
__device__ float g_sin  [TSEQ * 32];
// fp16 intermediates
__device__ hf g_qlin [MROWS * CEMB];
__device__ hf g_kvlin[MROWS * 2 * CEMB];
// fp16 activations (GEMM A operands)
__device__ hf g_h   [MROWS * CEMB];
__device__ hf g_ckva[MROWS * RKV];
__device__ hf g_ctx [MROWS * CEMB];
__device__ hf g_h2  [MROWS * CEMB];
__device__ hf g_ff1 [MROWS * FF];
// q/k/v fp16, [B,H,T,D]
__device__ hf g_q[MROWS * CEMB];
__device__ hf g_k[MROWS * CEMB];
__device__ hf g_v[MROWS * CEMB];
// fp16 transposed weights [N,K]
__device__ hf g_wq [CEMB * CEMB];
__device__ hf g_wkvd[RKV * CEMB];
__device__ hf g_wkvu[2 * CEMB * RKV];
__device__ hf g_wpr[CEMB * CEMB];
__device__ hf g_wf1[FF * CEMB];
__device__ hf g_wf2[CEMB * FF];

// ---------------------------------------------------------------------------
// Helpers
// ---------------------------------------------------------------------------
__device__ __forceinline__ uint32_t pack2h(float x, float y)
{
    __half2 p = __floats2half2_rn(x, y);
    return *(uint32_t*)&p;
}
__device__ __forceinline__ float gelu_exact(float x)
{
    return 0.5f * x * (1.0f + erff(x * 0.70710678118654752f));
}
__device__ __forceinline__ void cpa16(uint32_t saddr, const void* g)
{
    asm volatile("cp.async.cg.shared.global [%0], [%1], 16;"
                 :: "r"(saddr), "l"(g) : "memory");
}
__device__ __forceinline__ void cpa_commit()
{
    asm volatile("cp.async.commit_group;" ::: "memory");
}
template <int N>
__device__ __forceinline__ void cpa_wait()
{
    asm volatile("cp.async.wait_group %0;" :: "n"(N) : "memory");
}
__device__ __forceinline__ void mma_f16(float& c0, float& c1, float& c2, float& c3,
                                        uint32_t a0, uint32_t a1, uint32_t a2,
                                        uint32_t a3, uint32_t b0, uint32_t b1)
{
    asm volatile(
        "mma.sync.aligned.m16n8k16.row.col.f32.f16.f16.f32 "
        "{%0,%1,%2,%3}, {%4,%5,%6,%7}, {%8,%9}, {%0,%1,%2,%3};"
        : "+f"(c0), "+f"(c1), "+f"(c2), "+f"(c3)
        : "r"(a0), "r"(a1), "r"(a2), "r"(a3), "r"(b0), "r"(b1));
}
__device__ __forceinline__ void ldm4(uint32_t& r0, uint32_t& r1, uint32_t& r2,
                                     uint32_t& r3, uint32_t a)
{
    asm volatile("ldmatrix.sync.aligned.m8n8.x4.shared.b16 {%0,%1,%2,%3}, [%4];"
                 : "=r"(r0), "=r"(r1), "=r"(r2), "=r"(r3) : "r"(a));
}
__device__ __forceinline__ void ldm4t(uint32_t& r0, uint32_t& r1, uint32_t& r2,
                                      uint32_t& r3, uint32_t a)
{
    asm volatile("ldmatrix.sync.aligned.m8n8.x4.trans.shared.b16 {%0,%1,%2,%3}, [%4];"
                 : "=r"(r0), "=r"(r1), "=r"(r2), "=r"(r3) : "r"(a));
}

// ---------------------------------------------------------------------------
// LayerNorm: writes f32 or fp16
// ---------------------------------------------------------------------------
template <bool HOUT>
__global__ void __launch_bounds__(256) ln_k(const float* __restrict__ x,
                                            const float* __restrict__ w,
                                            const float* __restrict__ b,
                                            float* __restrict__ out,
                                            hf* __restrict__ oh, int W)
{
    size_t row = blockIdx.x;
    const float* xr = x + row * (size_t)W;

    float s = 0.f, s2 = 0.f;
    for (int i = threadIdx.x << 2; i < W; i += 256 * 4) {
        float4 v = *(const float4*)(xr + i);
        s  += v.x + v.y + v.z + v.w;
        s2 += v.x * v.x + v.y * v.y + v.z * v.z + v.w * v.w;
    }
    __shared__ float sh[8][2];
    #pragma unroll
    for (int off = 16; off; off >>= 1) {
        s  += __shfl_xor_sync(0xffffffffu, s,  off);
        s2 += __shfl_xor_sync(0xffffffffu, s2, off);
    }
    int wrp = threadIdx.x >> 5, ln = threadIdx.x & 31;
    if (ln == 0) { sh[wrp][0] = s; sh[wrp][1] = s2; }
    __syncthreads();
    s = 0.f; s2 = 0.f;
    #pragma unroll
    for (int i = 0; i < 8; i++) { s += sh[i][0]; s2 += sh[i][1]; }

    float invW = 1.0f / (float)W;
    float mu   = s * invW;
    float var  = s2 * invW - mu * mu;
    float rstd = rsqrtf(var + 1e-5f);

    for (int i = threadIdx.x << 2; i < W; i += 256 * 4) {
        float4 v  = *(const float4*)(xr + i);
        float4 wv = *(const float4*)(w + i);
        float4 bv = *(const float4*)(b + i);
        float r0 = (v.x - mu) * rstd * wv.x + bv.x;
        float r1 = (v.y - mu) * rstd * wv.y + bv.y;
        float r2 = (v.z - mu) * rstd * wv.z + bv.z;
        float r3 = (v.w - mu) * rstd * wv.w + bv.w;
        if (!HOUT) {
            *(float4*)(out + row * (size_t)W + i) = make_float4(r0, r1, r2, r3);
        } else {
            *(uint32_t*)(oh + row * (size_t)W + i)     = pack2h(r0, r1);
            *(uint32_t*)(oh + row * (size_t)W + i + 2) = pack2h(r2, r3);
        }
    }
}

// ---------------------------------------------------------------------------
// Weight preprocess: W[K,N] -> T [N,K] fp16 (tiled transpose)
// ---------------------------------------------------------------------------
__global__ void __launch_bounds__(256) prep_w(const float* __restrict__ W,
                                              hf* __restrict__ T,
                                              int K, int N)
{
    __shared__ float t[32][33];
    int nb = blockIdx.x * 32, kb = blockIdx.y * 32;
    int tx = threadIdx.x & 31, ty = threadIdx.x >> 5;  // 32 x 8
    #pragma unroll
    for (int j = 0; j < 32; j += 8)
        t[ty + j][tx] = W[(size_t)(kb + ty + j) * N + nb + tx];
    __syncthreads();
    #pragma unroll
    for (int j = 0; j < 32; j += 8)
        T[(size_t)(nb + ty + j) * K + kb + tx] = __float2half_rn(t[tx][ty + j]);
}

// ---------------------------------------------------------------------------
// RoPE table + fused RoPE/transpose (fp16 in) -> fp16 q/k/v [B,H,T,D]
// ---------------------------------------------------------------------------
__global__ void rope_tab_k(float* __restrict__ ct, float* __restrict__ st)
{
    int idx = blockIdx.x * blockDim.x + threadIdx.x;
    if (idx >= TSEQ * 32) return;
    int t = idx >> 5, d = idx & 31;
    float inv = (float)pow(10000.0, -(double)d / 32.0);
    float ang = (float)t * inv;
    ct[idx] = (float)cos((double)ang);
    st[idx] = (float)sin((double)ang);
}

__global__ void __launch_bounds__(256) rope_qkv_k(
    const hf* __restrict__ qlin, const hf* __restrict__ kvlin,
    const float* __restrict__ ct, const float* __restrict__ st,
    hf* __restrict__ q, hf* __restrict__ k, hf* __restrict__ v)
{
    int g = blockIdx.x * blockDim.x + threadIdx.x;
    int d = g & 31;
    int h = (g >> 5) & 15;
    int t = (g >> 9) & 2047;
    int b = g >> 20;

    float c = ct[t * 32 + d];
    float s = st[t * 32 + d];

    const hf* qlp = qlin + ((size_t)(b * TSEQ + t)) * CEMB + h * HD;
    const hf* klp = kvlin + ((size_t)(b * TSEQ + t)) * (2 * CEMB) + h * HD;
    const hf* vlp = klp + CEMB;

    size_t o = (((size_t)(b * NH + h)) * TSEQ + t) * HD;

    float q0 = __half2float(qlp[d]), q1 = __half2float(qlp[d + 32]);
    q[o + d]      = __float2half_rn(q0 * c - q1 * s);
    q[o + d + 32] = __float2half_rn(q1 * c + q0 * s);

    float k0 = __half2float(klp[d]), k1 = __half2float(klp[d + 32]);
    k[o + d]      = __float2half_rn(k0 * c - k1 * s);
    k[o + d + 32] = __float2half_rn(k1 * c + k0 * s);

    v[o + d]      = vlp[d];
    v[o + d + 32] = vlp[d + 32];
}

// ---------------------------------------------------------------------------
// mma.sync fp16 GEMM (1-pass): C[M,N] = A[M,K] @ W[N,K]^T.
// BM=BN=128, BK=32, 8 warps (2x4), warp tile 64x32. ROWP=40 (conflict-free).
// 2-stage cp.async, 40KB static smem, 2 CTAs/SM. Per-tile grid (R10 layout).
// ---------------------------------------------------------------------------
#define EPI_NONE       0
#define EPI_BIAS_RESID 1
#define EPI_BIAS_GELU  2

#define ROWP   40
#define MATB   (128 * ROWP * 2)     // 10240 bytes
#define STAGEB (2 * MATB)           // A, B

template <int EPI, int HOUT>
__global__ void __launch_bounds__(256, 2) gemm_mma(
    const hf* __restrict__ A, const hf* __restrict__ B,
    float* __restrict__ C, hf* __restrict__ Ch,
    const float* __restrict__ bias, const float* __restrict__ resid,
    int M, int N, int K)
{
    __shared__ char smem_raw[2 * STAGEB];   // 40960
    uint32_t smem_u = (uint32_t)__cvta_generic_to_shared(smem_raw);

    int tid = threadIdx.x;
    int wid = tid >> 5, lid = tid & 31;
    int wm = wid & 1, wn = wid >> 1;
    int qr = lid >> 2, qc = lid & 3;
    int bm = blockIdx.y * 128, bn = blockIdx.x * 128;

    const hf* Ap = A + (size_t)bm * K;
    const hf* Bp = B + (size_t)bn * K;

    int NK = K >> 5;    // BK = 32

    int lrow = tid >> 2;            // 0..63 base rows (2 chunks/thread)
    int lc8  = (tid & 3) << 3;      // 0,8,16,24

    auto stage_load = [&](int kt, int buf) {
        #pragma unroll
        for (int i = 0; i < 2; i++) {
            int row = lrow + i * 64;
            size_t go = (size_t)row * K + (kt << 5) + lc8;
            uint32_t sa = smem_u + buf * STAGEB + ((uint32_t)row * ROWP + lc8) * 2u;
            cpa16(sa + 0 * MATB, Ap + go);
            cpa16(sa + 1 * MATB, Bp + go);
        }
        cpa_commit();
    };

    int arow = wm * 64 + ((lid >> 3) & 1) * 8 + (lid & 7);
    int acolb = ((lid >> 4) & 1) * 8;
    int brow = wn * 32 + ((lid >> 4) & 1) * 8 + (lid & 7);
    int bcolb = ((lid >> 3) & 1) * 8;

    float acc[4][4][4] = {};

    stage_load(0, 0);

    for (int kt = 0; kt < NK; kt++) {
        int buf = kt & 1;
        if (kt + 1 < NK) {
            stage_load(kt + 1, buf ^ 1);
            cpa_wait<1>();
        } else {
            cpa_wait<0>();
        }
        __syncthreads();

        uint32_t sA = smem_u + buf * STAGEB + 0 * MATB;
        uint32_t sB = smem_u + buf * STAGEB + 1 * MATB;

        #pragma unroll
        for (int kh = 0; kh < 2; kh++) {
            int kc = kh * 16;
            uint32_t fa[4][4], fb[4][2];
            #pragma unroll
            for (int mi = 0; mi < 4; mi++)
                ldm4(fa[mi][0], fa[mi][1], fa[mi][2], fa[mi][3],
                     sA + ((uint32_t)((arow + mi * 16) * ROWP + kc + acolb)) * 2u);
            #pragma unroll
            for (int p = 0; p < 2; p++)
                ldm4(fb[2 * p][0], fb[2 * p][1], fb[2 * p + 1][0], fb[2 * p + 1][1],
                     sB + ((uint32_t)((brow + p * 16) * ROWP + kc + bcolb)) * 2u);
            #pragma unroll
            for (int ni = 0; ni < 4; ni++)
                #pragma unroll
                for (int mi = 0; mi < 4; mi++)
                    mma_f16(acc[mi][ni][0], acc[mi][ni][1],
                            acc[mi][ni][2], acc[mi][ni][3],
                            fa[mi][0], fa[mi][1], fa[mi][2], fa[mi][3],
                            fb[ni][0], fb[ni][1]);
        }
        __syncthreads();
    }

    #pragma unroll
    for (int mi = 0; mi < 4; mi++) {
        #pragma unroll
        for (int ni = 0; ni < 4; ni++) {
            int col = bn + wn * 32 + ni * 8 + qc * 2;
            #pragma unroll
            for (int half = 0; half < 2; half++) {
                int row = bm + wm * 64 + mi * 16 + qr + half * 8;
                size_t off = (size_t)row * N + col;
                float v0 = acc[mi][ni][half * 2 + 0];
                float v1 = acc[mi][ni][half * 2 + 1];
                if (EPI != EPI_NONE) {
                    v0 += bias[col];
                    v1 += bias[col + 1];
                }
                if (EPI == EPI_BIAS_GELU) {
                    v0 = gelu_exact(v0);
                    v1 = gelu_exact(v1);
                }
                if (EPI == EPI_BIAS_RESID) {
                    float2 rv = *(const float2*)(resid + off);
                    v0 += rv.x; v1 += rv.y;
                }
                if (!HOUT) {
                    *(float2*)(C + off) = make_float2(v0, v1);
                } else {
                    *(uint32_t*)(Ch + off) = pack2h(v0, v1);
                }
            }
        }
    }
}

// ---------------------------------------------------------------------------
// Flash attention, fp16 mma.sync, DOUBLE-BUFFERED K/V. Br=128, Bc=64,
// 8 warps x 16 rows. 36KB static smem (2 x (K 9KB + V 9KB)).
// ---------------------------------------------------------------------------
#define APAD 72
#define KVMAT (64 * APAD * 2)    // 9216 bytes per 64x64 matrix

__global__ void __launch_bounds__(256) attn_mma(
    const hf* __restrict__ q_, const hf* __restrict__ k_,
    const hf* __restrict__ v_, hf* __restrict__ ctx)
{
    __shared__ char sm[4 * KVMAT];   // 36864 bytes; buffer b at b*2*KVMAT
    uint32_t smu = (uint32_t)__cvta_generic_to_shared(sm);

    int b = blockIdx.z, h = blockIdx.y, it = blockIdx.x;
    int t0 = it * 128;
    size_t bh = ((size_t)(b * NH + h)) * TSEQ * HD;

    int tid = threadIdx.x;
    int w = tid >> 5, lid = tid & 31;
    int qr = lid >> 2, qc = lid & 3;

    // ---- stage Q (128x64) in low smem, ldmatrix into registers ----
    {
        const hf* src = q_ + bh + (size_t)t0 * HD;
        #pragma unroll
        for (int i = 0; i < 4; i++) {
            int chunk = tid + i * 256;
            int row = chunk >> 3, c8 = (chunk & 7) << 3;
            cpa16(smu + (row * APAD + c8) * 2, src + (size_t)row * HD + c8);
        }
        cpa_commit();
        cpa_wait<0>();
    }
    __syncthreads();

    uint32_t qa[4][4];
    {
        int row = w * 16 + ((lid >> 3) & 1) * 8 + (lid & 7);
        int colb = (lid >> 4) * 8;
        #pragma unroll
        for (int ks = 0; ks < 4; ks++) {
            uint32_t off = (uint32_t)(row * APAD + colb + ks * 16) * 2;
            ldm4(qa[ks][0], qa[ks][1], qa[ks][2], qa[ks][3], smu + off);
        }
    }
    __syncthreads();   // all warps hold Q in regs before buffer 0 is overwritten

    float m_i[2] = { -1e30f, -1e30f };
    float l_i[2] = { 0.f, 0.f };
    float o[8][4] = {};
    float s[8][4];

    int nrb = ((lid >> 4) & 1) * 8 + (lid & 7);
    int ncb = ((lid >> 3) & 1) * 8;
    int srb = ((lid >> 3) & 1) * 8 + (lid & 7);
    int scb = ((lid >> 4) & 1) * 8;

    // K/V loader into buffer bf
    auto load_kv = [&](int kt, int bf) {
        int k0 = kt * 64;
        const hf* srcs[2] = { k_ + bh + (size_t)k0 * HD,
                              v_ + bh + (size_t)k0 * HD };
        uint32_t base = smu + (uint32_t)bf * (2 * KVMAT);
        #pragma unroll
        for (int i = 0; i < 4; i++) {
            int chunk = tid + i * 256;
            int mat = chunk >> 9;
            int wi = chunk & 511;
            int row = wi >> 3, c8 = (wi & 7) << 3;
            cpa16(base + mat * KVMAT + (row * APAD + c8) * 2,
                  srcs[mat] + (size_t)row * HD + c8);
        }
        cpa_commit();
    };

    int nk = 2 * (it + 1);
    load_kv(0, 0);   // prologue

    for (int kt = 0; kt < nk; kt++) {
        int bf = kt & 1;
        if (kt + 1 < nk) {
            load_kv(kt + 1, bf ^ 1);
            cpa_wait<1>();
        } else {
            cpa_wait<0>();
        }
        __syncthreads();

        uint32_t kbase = smu + (uint32_t)bf * (2 * KVMAT);
        uint32_t vbase = kbase + KVMAT;
        int k0 = kt * 64;

        // ---- S = Q K^T ----
        #pragma unroll
        for (int nt = 0; nt < 8; nt++) {
            s[nt][0] = 0.f; s[nt][1] = 0.f; s[nt][2] = 0.f; s[nt][3] = 0.f;
        }
        #pragma unroll
        for (int ks = 0; ks < 4; ks++) {
            uint32_t kb[8][2];
            #pragma unroll
            for (int g = 0; g < 4; g++) {
                uint32_t a = kbase +
                             (uint32_t)((g * 16 + nrb) * APAD + ks * 16 + ncb) * 2;
                ldm4(kb[2 * g][0], kb[2 * g][1], kb[2 * g + 1][0], kb[2 * g + 1][1], a);
            }
            #pragma unroll
            for (int nt = 0; nt < 8; nt++)
                mma_f16(s[nt][0], s[nt][1], s[nt][2], s[nt][3],
                        qa[ks][0], qa[ks][1], qa[ks][2], qa[ks][3],
                        kb[nt][0], kb[nt][1]);
        }

        int row0 = t0 + w * 16 + qr;
        int row1 = row0 + 8;
        #pragma unroll
        for (int nt = 0; nt < 8; nt++) {
            int col0 = k0 + nt * 8 + qc * 2;
            s[nt][0] = (col0     > row0) ? -1e30f : s[nt][0] * 0.125f;
            s[nt][1] = (col0 + 1 > row0) ? -1e30f : s[nt][1] * 0.125f;
            s[nt][2] = (col0     > row1) ? -1e30f : s[nt][2] * 0.125f;
            s[nt][3] = (col0 + 1 > row1) ? -1e30f : s[nt][3] * 0.125f;
        }

        float mxA = -1e30f, mxB = -1e30f;
        #pragma unroll
        for (int nt = 0; nt < 8; nt++) {
            mxA = fmaxf(mxA, fmaxf(s[nt][0], s[nt][1]));
            mxB = fmaxf(mxB, fmaxf(s[nt][2], s[nt][3]));
        }
        mxA = fmaxf(mxA, __shfl_xor_sync(0xffffffffu, mxA, 1));
        mxA = fmaxf(mxA, __shfl_xor_sync(0xffffffffu, mxA, 2));
        mxB = fmaxf(mxB, __shfl_xor_sync(0xffffffffu, mxB, 1));
        mxB = fmaxf(mxB, __shfl_xor_sync(0xffffffffu, mxB, 2));

        float mnA = fmaxf(m_i[0], mxA), mnB = fmaxf(m_i[1], mxB);
        float aA = expf(m_i[0] - mnA), aB = expf(m_i[1] - mnB);
        m_i[0] = mnA; m_i[1] = mnB;

        float sumA = 0.f, sumB = 0.f;
        #pragma unroll
        for (int nt = 0; nt < 8; nt++) {
            s[nt][0] = expf(s[nt][0] - mnA); sumA += s[nt][0];
            s[nt][1] = expf(s[nt][1] - mnA); sumA += s[nt][1];
            s[nt][2] = expf(s[nt][2] - mnB); sumB += s[nt][2];
            s[nt][3] = expf(s[nt][3] - mnB); sumB += s[nt][3];
        }
        sumA += __shfl_xor_sync(0xffffffffu, sumA, 1);
        sumA += __shfl_xor_sync(0xffffffffu, sumA, 2);
        sumB += __shfl_xor_sync(0xffffffffu, sumB, 1);
        sumB += __shfl_xor_sync(0xffffffffu, sumB, 2);
        l_i[0] = l_i[0] * aA + sumA;
        l_i[1] = l_i[1] * aB + sumB;

        #pragma unroll
        for (int dt = 0; dt < 8; dt++) {
            o[dt][0] *= aA; o[dt][1] *= aA;
            o[dt][2] *= aB; o[dt][3] *= aB;
        }

        // ---- O += P V ----
        #pragma unroll
        for (int ks = 0; ks < 4; ks++) {
            uint32_t pa[4];
            pa[0] = pack2h(s[2 * ks][0],     s[2 * ks][1]);
            pa[1] = pack2h(s[2 * ks][2],     s[2 * ks][3]);
            pa[2] = pack2h(s[2 * ks + 1][0], s[2 * ks + 1][1]);
            pa[3] = pack2h(s[2 * ks + 1][2], s[2 * ks + 1][3]);

            uint32_t vb[8][2];
            #pragma unroll
            for (int g = 0; g < 4; g++) {
                uint32_t a = vbase +
                             (uint32_t)((ks * 16 + srb) * APAD + g * 16 + scb) * 2;
                ldm4t(vb[2 * g][0], vb[2 * g][1], vb[2 * g + 1][0], vb[2 * g + 1][1], a);
            }
            #pragma unroll
            for (int dt = 0; dt < 8; dt++)
                mma_f16(o[dt][0], o[dt][1], o[dt][2], o[dt][3],
                        pa[0], pa[1], pa[2], pa[3], vb[dt][0], vb[dt][1]);
        }
        __syncthreads();   // next iter's prefetch overwrites this buffer
    }

    float invA = 1.0f / l_i[0], invB = 1.0f / l_i[1];
    int r0 = t0 + w * 16 + qr, r1 = r0 + 8;
    #pragma unroll
    for (int dt = 0; dt < 8; dt++) {
        int col = h * HD + dt * 8 + qc * 2;
        size_t off0 = ((size_t)(b * TSEQ + r0)) * CEMB + col;
        *(uint32_t*)(ctx + off0) = pack2h(o[dt][0] * invA, o[dt][1] * invA);
        size_t off1 = ((size_t)(b * TSEQ + r1)) * CEMB + col;
        *(uint32_t*)(ctx + off1) = pack2h(o[dt][2] * invB, o[dt][3] * invB);
    }
}

// ---------------------------------------------------------------------------
// Launch (indices 3 AND 5 are main GEMMs for ncu capture)
// ---------------------------------------------------------------------------
static float* sym(const void* s)
{
    void* p = nullptr;
    cudaGetSymbolAddress(&p, s);
    return (float*)p;
}
static hf* symh(const void* s)
{
    void* p = nullptr;
    cudaGetSymbolAddress(&p, s);
    return (hf*)p;
}

extern "C" void kernel_launch(void* const* d_in, const int* in_sizes, int n_in,
                              void* d_out, int out_size)
{
    const float* x      = (const float*)d_in[0];
    const float* ln1_w  = (const float*)d_in[1];
    const float* ln1_b  = (const float*)d_in[2];
    const float* ln2_w  = (const float*)d_in[3];
    const float* ln2_b  = (const float*)d_in[4];
    const float* q_w    = (const float*)d_in[5];
    const float* kvd_w  = (const float*)d_in[6];
    const float* kvln_w = (const float*)d_in[7];
    const float* kvln_b = (const float*)d_in[8];
    const float* kvu_w  = (const float*)d_in[9];
    const float* proj_w = (const float*)d_in[10];
    const float* proj_b = (const float*)d_in[11];
    const float* f1_w   = (const float*)d_in[12];
    const float* f1_b   = (const float*)d_in[13];
    const float* f2_w   = (const float*)d_in[14];
    const float* f2_b   = (const float*)d_in[15];
    float* out = (float*)d_out;

    float* ckv   = sym(g_ckv);
    float* x1    = sym(g_x1);
    float* ct    = sym(g_cos);
    float* st    = sym(g_sin);
    hf *qlin  = symh(g_qlin);
    hf *kvlin = symh(g_kvlin);
    hf *hh  = symh(g_h);
    hf *cva = symh(g_ckva);
    hf *ctx = symh(g_ctx);
    hf *h2  = symh(g_h2);
    hf *ff1 = symh(g_ff1);
    hf *q = symh(g_q), *k = symh(g_k), *v = symh(g_v);
    hf *wq = symh(g_wq), *wd = symh(g_wkvd), *wu = symh(g_wkvu);
    hf *wp = symh(g_wpr), *w1 = symh(g_wf1), *w2 = symh(g_wf2);

    // 0: prep q_w
    prep_w<<<dim3(CEMB / 32, CEMB / 32), 256>>>(q_w, wq, CEMB, CEMB);
    // 1: h = LN1(x) -> fp16
    ln_k<true><<<MROWS, 256>>>(x, ln1_w, ln1_b, nullptr, hh, CEMB);
    // 2: prep kvd_w
    prep_w<<<dim3(RKV / 32, CEMB / 32), 256>>>(kvd_w, wd, CEMB, RKV);
    // 3: qlin = h @ q_w -> fp16      <-- ncu target (offset 2)
    gemm_mma<EPI_NONE, 1><<<dim3(CEMB / 128, MROWS / 128), 256>>>(
        hh, wq, nullptr, qlin, nullptr, nullptr, MROWS, CEMB, CEMB);
    // 4: prep kvu_w
    prep_w<<<dim3(2 * CEMB / 32, RKV / 32), 256>>>(kvu_w, wu, RKV, 2 * CEMB);
    // 5: ckv = h @ kvd_w (f32)       <-- ncu target (offset 0)
    gemm_mma<EPI_NONE, 0><<<dim3(RKV / 128, MROWS / 128), 256>>>(
        hh, wd, ckv, nullptr, nullptr, nullptr, MROWS, RKV, CEMB);
    // 6: ckv = LN_kv(ckv) -> fp16
    ln_k<true><<<MROWS, 256>>>(ckv, kvln_w, kvln_b, nullptr, cva, RKV);
    // 7: kvlin = ckv @ kvu_w -> fp16
    gemm_mma<EPI_NONE, 1><<<dim3(2 * CEMB / 128, MROWS / 128), 256>>>(
        cva, wu, nullptr, kvlin, nullptr, nullptr, MROWS, 2 * CEMB, RKV);
    // 8: prep proj_w
    prep_w<<<dim3(CEMB / 32, CEMB / 32), 256>>>(proj_w, wp, CEMB, CEMB);
    // 9/10: rope
    rope_tab_k<<<(TSEQ * 32 + 255) / 256, 256>>>(ct, st);
    rope_qkv_k<<<(BSZ * TSEQ * NH * 32) / 256, 256>>>(qlin, kvlin, ct, st, q, k, v);
    // 11: flash attention (double-buffered)
    attn_mma<<<dim3(TSEQ / 128, NH, BSZ), 256>>>(q, k, v, ctx);
    // 12: x1 = x + ctx @ proj_w + proj_b (f32)
    gemm_mma<EPI_BIAS_RESID, 0><<<dim3(CEMB / 128, MROWS / 128), 256>>>(
        ctx, wp, x1, nullptr, proj_b, x, MROWS, CEMB, CEMB);
    // 13: h2 = LN2(x1) -> fp16
    ln_k<true><<<MROWS, 256>>>(x1, ln2_w, ln2_b, nullptr, h2, CEMB);
    // 14: prep f1_w
    prep_w<<<dim3(FF / 32, CEMB / 32), 256>>>(f1_w, w1, CEMB, FF);
    // 15: ff1 = gelu(h2 @ f1_w + f1_b) -> fp16
    gemm_mma<EPI_BIAS_GELU, 1><<<dim3(FF / 128, MROWS / 128), 256>>>(
        h2, w1, nullptr, ff1, f1_b, nullptr, MROWS, FF, CEMB);
    // 16: prep f2_w
    prep_w<<<dim3(CEMB / 32, FF / 32), 256>>>(f2_w, w2, FF, CEMB);
    // 17: out = x1 + ff1 @ f2_w + f2_b (f32)
    gemm_mma<EPI_BIAS_RESID, 0><<<dim3(CEMB / 128, MROWS / 128), 256>>>(
        ff1, w2, out, nullptr, f2_b, x1, MROWS, CEMB, FF);
}

// round 16
// speedup vs baseline: 1.3747x; 1.0242x over previous
#include <cuda_runtime.h>
#include <cuda_fp16.h>
#include <math.h>
#include <stdint.h>

// ---------------------------------------------------------------------------
// Problem constants
// ---------------------------------------------------------------------------
#define BSZ   4
#define TSEQ  2048
#define CEMB  1024
#define NH    16
#define HD    64
#define RKV   512
#define FF    4096
#define MROWS (BSZ * TSEQ)   // 8192

typedef __half hf;

// ---------------------------------------------------------------------------
// Scratch (static __device__ arrays -- allocation-free per harness rules)
// ---------------------------------------------------------------------------
__device__ float g_ckv  [MROWS * RKV];
__device__ float g_x1   [MROWS * CEMB];
__device__ float g_cos  [TSEQ * 32];
__device__ float g_sin  [TSEQ * 32];
// fp16 intermediates
__device__ hf g_qlin [MROWS * CEMB];
__device__ hf g_kvlin[MROWS * 2 * CEMB];
// fp16 activations (GEMM A operands)
__device__ hf g_h   [MROWS * CEMB];
__device__ hf g_ckva[MROWS * RKV];
__device__ hf g_ctx [MROWS * CEMB];
__device__ hf g_h2  [MROWS * CEMB];
__device__ hf g_ff1 [MROWS * FF];
// q/k/v fp16, [B,H,T,D]
__device__ hf g_q[MROWS * CEMB];
__device__ hf g_k[MROWS * CEMB];
__device__ hf g_v[MROWS * CEMB];
// fp16 transposed weights [N,K]
__device__ hf g_wq [CEMB * CEMB];
__device__ hf g_wkvd[RKV * CEMB];
__device__ hf g_wkvu[2 * CEMB * RKV];
__device__ hf g_wpr[CEMB * CEMB];
__device__ hf g_wf1[FF * CEMB];
__device__ hf g_wf2[CEMB * FF];

// ---------------------------------------------------------------------------
// Helpers
// ---------------------------------------------------------------------------
__device__ __forceinline__ uint32_t pack2h(float x, float y)
{
    __half2 p = __floats2half2_rn(x, y);
    return *(uint32_t*)&p;
}
__device__ __forceinline__ float gelu_exact(float x)
{
    return 0.5f * x * (1.0f + erff(x * 0.70710678118654752f));
}
__device__ __forceinline__ void cpa16(uint32_t saddr, const void* g)
{
    asm volatile("cp.async.cg.shared.global [%0], [%1], 16;"
                 :: "r"(saddr), "l"(g) : "memory");
}
__device__ __forceinline__ void cpa_commit()
{
    asm volatile("cp.async.commit_group;" ::: "memory");
}
template <int N>
__device__ __forceinline__ void cpa_wait()
{
    asm volatile("cp.async.wait_group %0;" :: "n"(N) : "memory");
}
__device__ __forceinline__ void mma_f16(float& c0, float& c1, float& c2, float& c3,
                                        uint32_t a0, uint32_t a1, uint32_t a2,
                                        uint32_t a3, uint32_t b0, uint32_t b1)
{
    asm volatile(
        "mma.sync.aligned.m16n8k16.row.col.f32.f16.f16.f32 "
        "{%0,%1,%2,%3}, {%4,%5,%6,%7}, {%8,%9}, {%0,%1,%2,%3};"
        : "+f"(c0), "+f"(c1), "+f"(c2), "+f"(c3)
        : "r"(a0), "r"(a1), "r"(a2), "r"(a3), "r"(b0), "r"(b1));
}
__device__ __forceinline__ void ldm4(uint32_t& r0, uint32_t& r1, uint32_t& r2,
                                     uint32_t& r3, uint32_t a)
{
    asm volatile("ldmatrix.sync.aligned.m8n8.x4.shared.b16 {%0,%1,%2,%3}, [%4];"
                 : "=r"(r0), "=r"(r1), "=r"(r2), "=r"(r3) : "r"(a));
}
__device__ __forceinline__ void ldm4t(uint32_t& r0, uint32_t& r1, uint32_t& r2,
                                      uint32_t& r3, uint32_t a)
{
    asm volatile("ldmatrix.sync.aligned.m8n8.x4.trans.shared.b16 {%0,%1,%2,%3}, [%4];"
                 : "=r"(r0), "=r"(r1), "=r"(r2), "=r"(r3) : "r"(a));
}

// ---------------------------------------------------------------------------
// LayerNorm: writes f32 or fp16
// ---------------------------------------------------------------------------
template <bool HOUT>
__global__ void __launch_bounds__(256) ln_k(const float* __restrict__ x,
                                            const float* __restrict__ w,
                                            const float* __restrict__ b,
                                            float* __restrict__ out,
                                            hf* __restrict__ oh, int W)
{
    size_t row = blockIdx.x;
    const float* xr = x + row * (size_t)W;

    float s = 0.f, s2 = 0.f;
    for (int i = threadIdx.x << 2; i < W; i += 256 * 4) {
        float4 v = *(const float4*)(xr + i);
        s  += v.x + v.y + v.z + v.w;
        s2 += v.x * v.x + v.y * v.y + v.z * v.z + v.w * v.w;
    }
    __shared__ float sh[8][2];
    #pragma unroll
    for (int off = 16; off; off >>= 1) {
        s  += __shfl_xor_sync(0xffffffffu, s,  off);
        s2 += __shfl_xor_sync(0xffffffffu, s2, off);
    }
    int wrp = threadIdx.x >> 5, ln = threadIdx.x & 31;
    if (ln == 0) { sh[wrp][0] = s; sh[wrp][1] = s2; }
    __syncthreads();
    s = 0.f; s2 = 0.f;
    #pragma unroll
    for (int i = 0; i < 8; i++) { s += sh[i][0]; s2 += sh[i][1]; }

    float invW = 1.0f / (float)W;
    float mu   = s * invW;
    float var  = s2 * invW - mu * mu;
    float rstd = rsqrtf(var + 1e-5f);

    for (int i = threadIdx.x << 2; i < W; i += 256 * 4) {
        float4 v  = *(const float4*)(xr + i);
        float4 wv = *(const float4*)(w + i);
        float4 bv = *(const float4*)(b + i);
        float r0 = (v.x - mu) * rstd * wv.x + bv.x;
        float r1 = (v.y - mu) * rstd * wv.y + bv.y;
        float r2 = (v.z - mu) * rstd * wv.z + bv.z;
        float r3 = (v.w - mu) * rstd * wv.w + bv.w;
        if (!HOUT) {
            *(float4*)(out + row * (size_t)W + i) = make_float4(r0, r1, r2, r3);
        } else {
            *(uint32_t*)(oh + row * (size_t)W + i)     = pack2h(r0, r1);
            *(uint32_t*)(oh + row * (size_t)W + i + 2) = pack2h(r2, r3);
        }
    }
}

// ---------------------------------------------------------------------------
// Weight preprocess: W[K,N] -> T [N,K] fp16 (tiled transpose)
// ---------------------------------------------------------------------------
__global__ void __launch_bounds__(256) prep_w(const float* __restrict__ W,
                                              hf* __restrict__ T,
                                              int K, int N)
{
    __shared__ float t[32][33];
    int nb = blockIdx.x * 32, kb = blockIdx.y * 32;
    int tx = threadIdx.x & 31, ty = threadIdx.x >> 5;  // 32 x 8
    #pragma unroll
    for (int j = 0; j < 32; j += 8)
        t[ty + j][tx] = W[(size_t)(kb + ty + j) * N + nb + tx];
    __syncthreads();
    #pragma unroll
    for (int j = 0; j < 32; j += 8)
        T[(size_t)(nb + ty + j) * K + kb + tx] = __float2half_rn(t[tx][ty + j]);
}

// ---------------------------------------------------------------------------
// RoPE table + fused RoPE/transpose (fp16 in) -> fp16 q/k/v [B,H,T,D]
// ---------------------------------------------------------------------------
__global__ void rope_tab_k(float* __restrict__ ct, float* __restrict__ st)
{
    int idx = blockIdx.x * blockDim.x + threadIdx.x;
    if (idx >= TSEQ * 32) return;
    int t = idx >> 5, d = idx & 31;
    float inv = (float)pow(10000.0, -(double)d / 32.0);
    float ang = (float)t * inv;
    ct[idx] = (float)cos((double)ang);
    st[idx] = (float)sin((double)ang);
}

__global__ void __launch_bounds__(256) rope_qkv_k(
    const hf* __restrict__ qlin, const hf* __restrict__ kvlin,
    const float* __restrict__ ct, const float* __restrict__ st,
    hf* __restrict__ q, hf* __restrict__ k, hf* __restrict__ v)
{
    int g = blockIdx.x * blockDim.x + threadIdx.x;
    int d = g & 31;
    int h = (g >> 5) & 15;
    int t = (g >> 9) & 2047;
    int b = g >> 20;

    float c = ct[t * 32 + d];
    float s = st[t * 32 + d];

    const hf* qlp = qlin + ((size_t)(b * TSEQ + t)) * CEMB + h * HD;
    const hf* klp = kvlin + ((size_t)(b * TSEQ + t)) * (2 * CEMB) + h * HD;
    const hf* vlp = klp + CEMB;

    size_t o = (((size_t)(b * NH + h)) * TSEQ + t) * HD;

    float q0 = __half2float(qlp[d]), q1 = __half2float(qlp[d + 32]);
    q[o + d]      = __float2half_rn(q0 * c - q1 * s);
    q[o + d + 32] = __float2half_rn(q1 * c + q0 * s);

    float k0 = __half2float(klp[d]), k1 = __half2float(klp[d + 32]);
    k[o + d]      = __float2half_rn(k0 * c - k1 * s);
    k[o + d + 32] = __float2half_rn(k1 * c + k0 * s);

    v[o + d]      = vlp[d];
    v[o + d + 32] = vlp[d + 32];
}

// ---------------------------------------------------------------------------
// mma.sync fp16 GEMM (1-pass): C[M,N] = A[M,K] @ W[N,K]^T.
// BM=BN=128, BK=32, 8 warps (2x4), warp tile 64x32. ROWP=40 (conflict-free).
// 2-stage cp.async with SINGLE sync per K-iteration:
//   wait -> sync -> issue(kt+1 -> buf^1) -> compute(buf)
// The one sync is after all waits (copies visible) AND after all kt-1 reads
// of buf^1 (WAR-safe for the new writes). 40KB static smem, 2 CTAs/SM.
// ---------------------------------------------------------------------------
#define EPI_NONE       0
#define EPI_BIAS_RESID 1
#define EPI_BIAS_GELU  2

#define ROWP   40
#define MATB   (128 * ROWP * 2)     // 10240 bytes
#define STAGEB (2 * MATB)           // A, B

template <int EPI, int HOUT>
__global__ void __launch_bounds__(256, 2) gemm_mma(
    const hf* __restrict__ A, const hf* __restrict__ B,
    float* __restrict__ C, hf* __restrict__ Ch,
    const float* __restrict__ bias, const float* __restrict__ resid,
    int M, int N, int K)
{
    __shared__ char smem_raw[2 * STAGEB];   // 40960
    uint32_t smem_u = (uint32_t)__cvta_generic_to_shared(smem_raw);

    int tid = threadIdx.x;
    int wid = tid >> 5, lid = tid & 31;
    int wm = wid & 1, wn = wid >> 1;
    int qr = lid >> 2, qc = lid & 3;
    int bm = blockIdx.y * 128, bn = blockIdx.x * 128;

    const hf* Ap = A + (size_t)bm * K;
    const hf* Bp = B + (size_t)bn * K;

    int NK = K >> 5;    // BK = 32

    int lrow = tid >> 2;            // 0..63 base rows (2 chunks/thread)
    int lc8  = (tid & 3) << 3;      // 0,8,16,24

    auto stage_load = [&](int kt, int buf) {
        #pragma unroll
        for (int i = 0; i < 2; i++) {
            int row = lrow + i * 64;
            size_t go = (size_t)row * K + (kt << 5) + lc8;
            uint32_t sa = smem_u + buf * STAGEB + ((uint32_t)row * ROWP + lc8) * 2u;
            cpa16(sa + 0 * MATB, Ap + go);
            cpa16(sa + 1 * MATB, Bp + go);
        }
        cpa_commit();
    };

    int arow = wm * 64 + ((lid >> 3) & 1) * 8 + (lid & 7);
    int acolb = ((lid >> 4) & 1) * 8;
    int brow = wn * 32 + ((lid >> 4) & 1) * 8 + (lid & 7);
    int bcolb = ((lid >> 3) & 1) * 8;

    float acc[4][4][4] = {};

    stage_load(0, 0);

    for (int kt = 0; kt < NK; kt++) {
        int buf = kt & 1;
        cpa_wait<0>();
        __syncthreads();
        if (kt + 1 < NK)
            stage_load(kt + 1, buf ^ 1);

        uint32_t sA = smem_u + buf * STAGEB + 0 * MATB;
        uint32_t sB = smem_u + buf * STAGEB + 1 * MATB;

        #pragma unroll
        for (int kh = 0; kh < 2; kh++) {
            int kc = kh * 16;
            uint32_t fa[4][4], fb[4][2];
            #pragma unroll
            for (int mi = 0; mi < 4; mi++)
                ldm4(fa[mi][0], fa[mi][1], fa[mi][2], fa[mi][3],
                     sA + ((uint32_t)((arow + mi * 16) * ROWP + kc + acolb)) * 2u);
            #pragma unroll
            for (int p = 0; p < 2; p++)
                ldm4(fb[2 * p][0], fb[2 * p][1], fb[2 * p + 1][0], fb[2 * p + 1][1],
                     sB + ((uint32_t)((brow + p * 16) * ROWP + kc + bcolb)) * 2u);
            #pragma unroll
            for (int ni = 0; ni < 4; ni++)
                #pragma unroll
                for (int mi = 0; mi < 4; mi++)
                    mma_f16(acc[mi][ni][0], acc[mi][ni][1],
                            acc[mi][ni][2], acc[mi][ni][3],
                            fa[mi][0], fa[mi][1], fa[mi][2], fa[mi][3],
                            fb[ni][0], fb[ni][1]);
        }
    }

    #pragma unroll
    for (int mi = 0; mi < 4; mi++) {
        #pragma unroll
        for (int ni = 0; ni < 4; ni++) {
            int col = bn + wn * 32 + ni * 8 + qc * 2;
            #pragma unroll
            for (int half = 0; half < 2; half++) {
                int row = bm + wm * 64 + mi * 16 + qr + half * 8;
                size_t off = (size_t)row * N + col;
                float v0 = acc[mi][ni][half * 2 + 0];
                float v1 = acc[mi][ni][half * 2 + 1];
                if (EPI != EPI_NONE) {
                    v0 += bias[col];
                    v1 += bias[col + 1];
                }
                if (EPI == EPI_BIAS_GELU) {
                    v0 = gelu_exact(v0);
                    v1 = gelu_exact(v1);
                }
                if (EPI == EPI_BIAS_RESID) {
                    float2 rv = *(const float2*)(resid + off);
                    v0 += rv.x; v1 += rv.y;
                }
                if (!HOUT) {
                    *(float2*)(C + off) = make_float2(v0, v1);
                } else {
                    *(uint32_t*)(Ch + off) = pack2h(v0, v1);
                }
            }
        }
    }
}

// ---------------------------------------------------------------------------
// Flash attention, fp16 mma.sync, double-buffered K/V, SINGLE sync per iter.
// Heavy tiles first (it reversed) for tail-wave load balance.
// Br=128, Bc=64, 8 warps x 16 rows. 36KB static smem.
// ---------------------------------------------------------------------------
#define APAD 72
#define KVMAT (64 * APAD * 2)    // 9216 bytes per 64x64 matrix

__global__ void __launch_bounds__(256) attn_mma(
    const hf* __restrict__ q_, const hf* __restrict__ k_,
    const hf* __restrict__ v_, hf* __restrict__ ctx)
{
    __shared__ char sm[4 * KVMAT];   // 36864 bytes; buffer b at b*2*KVMAT
    uint32_t smu = (uint32_t)__cvta_generic_to_shared(sm);

    int b = blockIdx.z, h = blockIdx.y;
    int it = gridDim.x - 1 - blockIdx.x;   // heavy tiles launch first
    int t0 = it * 128;
    size_t bh = ((size_t)(b * NH + h)) * TSEQ * HD;

    int tid = threadIdx.x;
    int w = tid >> 5, lid = tid & 31;
    int qr = lid >> 2, qc = lid & 3;

    // ---- stage Q (128x64) in low smem, ldmatrix into registers ----
    {
        const hf* src = q_ + bh + (size_t)t0 * HD;
        #pragma unroll
        for (int i = 0; i < 4; i++) {
            int chunk = tid + i * 256;
            int row = chunk >> 3, c8 = (chunk & 7) << 3;
            cpa16(smu + (row * APAD + c8) * 2, src + (size_t)row * HD + c8);
        }
        cpa_commit();
        cpa_wait<0>();
    }
    __syncthreads();

    uint32_t qa[4][4];
    {
        int row = w * 16 + ((lid >> 3) & 1) * 8 + (lid & 7);
        int colb = (lid >> 4) * 8;
        #pragma unroll
        for (int ks = 0; ks < 4; ks++) {
            uint32_t off = (uint32_t)(row * APAD + colb + ks * 16) * 2;
            ldm4(qa[ks][0], qa[ks][1], qa[ks][2], qa[ks][3], smu + off);
        }
    }
    __syncthreads();   // all warps hold Q in regs before buffer 0 is overwritten

    float m_i[2] = { -1e30f, -1e30f };
    float l_i[2] = { 0.f, 0.f };
    float o[8][4] = {};
    float s[8][4];

    int nrb = ((lid >> 4) & 1) * 8 + (lid & 7);
    int ncb = ((lid >> 3) & 1) * 8;
    int srb = ((lid >> 3) & 1) * 8 + (lid & 7);
    int scb = ((lid >> 4) & 1) * 8;

    auto load_kv = [&](int kt, int bf) {
        int k0 = kt * 64;
        const hf* srcs[2] = { k_ + bh + (size_t)k0 * HD,
                              v_ + bh + (size_t)k0 * HD };
        uint32_t base = smu + (uint32_t)bf * (2 * KVMAT);
        #pragma unroll
        for (int i = 0; i < 4; i++) {
            int chunk = tid + i * 256;
            int mat = chunk >> 9;
            int wi = chunk & 511;
            int row = wi >> 3, c8 = (wi & 7) << 3;
            cpa16(base + mat * KVMAT + (row * APAD + c8) * 2,
                  srcs[mat] + (size_t)row * HD + c8);
        }
        cpa_commit();
    };

    int nk = 2 * (it + 1);
    load_kv(0, 0);   // prologue

    for (int kt = 0; kt < nk; kt++) {
        int bf = kt & 1;
        cpa_wait<0>();
        __syncthreads();
        if (kt + 1 < nk)
            load_kv(kt + 1, bf ^ 1);

        uint32_t kbase = smu + (uint32_t)bf * (2 * KVMAT);
        uint32_t vbase = kbase + KVMAT;
        int k0 = kt * 64;

        // ---- S = Q K^T ----
        #pragma unroll
        for (int nt = 0; nt < 8; nt++) {
            s[nt][0] = 0.f; s[nt][1] = 0.f; s[nt][2] = 0.f; s[nt][3] = 0.f;
        }
        #pragma unroll
        for (int ks = 0; ks < 4; ks++) {
            uint32_t kb[8][2];
            #pragma unroll
            for (int g = 0; g < 4; g++) {
                uint32_t a = kbase +
                             (uint32_t)((g * 16 + nrb) * APAD + ks * 16 + ncb) * 2;
                ldm4(kb[2 * g][0], kb[2 * g][1], kb[2 * g + 1][0], kb[2 * g + 1][1], a);
            }
            #pragma unroll
            for (int nt = 0; nt < 8; nt++)
                mma_f16(s[nt][0], s[nt][1], s[nt][2], s[nt][3],
                        qa[ks][0], qa[ks][1], qa[ks][2], qa[ks][3],
                        kb[nt][0], kb[nt][1]);
        }

        int row0 = t0 + w * 16 + qr;
        int row1 = row0 + 8;
        #pragma unroll
        for (int nt = 0; nt < 8; nt++) {
            int col0 = k0 + nt * 8 + qc * 2;
            s[nt][0] = (col0     > row0) ? -1e30f : s[nt][0] * 0.125f;
            s[nt][1] = (col0 + 1 > row0) ? -1e30f : s[nt][1] * 0.125f;
            s[nt][2] = (col0     > row1) ? -1e30f : s[nt][2] * 0.125f;
            s[nt][3] = (col0 + 1 > row1) ? -1e30f : s[nt][3] * 0.125f;
        }

        float mxA = -1e30f, mxB = -1e30f;
        #pragma unroll
        for (int nt = 0; nt < 8; nt++) {
            mxA = fmaxf(mxA, fmaxf(s[nt][0], s[nt][1]));
            mxB = fmaxf(mxB, fmaxf(s[nt][2], s[nt][3]));
        }
        mxA = fmaxf(mxA, __shfl_xor_sync(0xffffffffu, mxA, 1));
        mxA = fmaxf(mxA, __shfl_xor_sync(0xffffffffu, mxA, 2));
        mxB = fmaxf(mxB, __shfl_xor_sync(0xffffffffu, mxB, 1));
        mxB = fmaxf(mxB, __shfl_xor_sync(0xffffffffu, mxB, 2));

        float mnA = fmaxf(m_i[0], mxA), mnB = fmaxf(m_i[1], mxB);
        float aA = expf(m_i[0] - mnA), aB = expf(m_i[1] - mnB);
        m_i[0] = mnA; m_i[1] = mnB;

        float sumA = 0.f, sumB = 0.f;
        #pragma unroll
        for (int nt = 0; nt < 8; nt++) {
            s[nt][0] = expf(s[nt][0] - mnA); sumA += s[nt][0];
            s[nt][1] = expf(s[nt][1] - mnA); sumA += s[nt][1];
            s[nt][2] = expf(s[nt][2] - mnB); sumB += s[nt][2];
            s[nt][3] = expf(s[nt][3] - mnB); sumB += s[nt][3];
        }
        sumA += __shfl_xor_sync(0xffffffffu, sumA, 1);
        sumA += __shfl_xor_sync(0xffffffffu, sumA, 2);
        sumB += __shfl_xor_sync(0xffffffffu, sumB, 1);
        sumB += __shfl_xor_sync(0xffffffffu, sumB, 2);
        l_i[0] = l_i[0] * aA + sumA;
        l_i[1] = l_i[1] * aB + sumB;

        #pragma unroll
        for (int dt = 0; dt < 8; dt++) {
            o[dt][0] *= aA; o[dt][1] *= aA;
            o[dt][2] *= aB; o[dt][3] *= aB;
        }

        // ---- O += P V ----
        #pragma unroll
        for (int ks = 0; ks < 4; ks++) {
            uint32_t pa[4];
            pa[0] = pack2h(s[2 * ks][0],     s[2 * ks][1]);
            pa[1] = pack2h(s[2 * ks][2],     s[2 * ks][3]);
            pa[2] = pack2h(s[2 * ks + 1][0], s[2 * ks + 1][1]);
            pa[3] = pack2h(s[2 * ks + 1][2], s[2 * ks + 1][3]);

            uint32_t vb[8][2];
            #pragma unroll
            for (int g = 0; g < 4; g++) {
                uint32_t a = vbase +
                             (uint32_t)((ks * 16 + srb) * APAD + g * 16 + scb) * 2;
                ldm4t(vb[2 * g][0], vb[2 * g][1], vb[2 * g + 1][0], vb[2 * g + 1][1], a);
            }
            #pragma unroll
            for (int dt = 0; dt < 8; dt++)
                mma_f16(o[dt][0], o[dt][1], o[dt][2], o[dt][3],
                        pa[0], pa[1], pa[2], pa[3], vb[dt][0], vb[dt][1]);
        }
    }

    float invA = 1.0f / l_i[0], invB = 1.0f / l_i[1];
    int r0 = t0 + w * 16 + qr, r1 = r0 + 8;
    #pragma unroll
    for (int dt = 0; dt < 8; dt++) {
        int col = h * HD + dt * 8 + qc * 2;
        size_t off0 = ((size_t)(b * TSEQ + r0)) * CEMB + col;
        *(uint32_t*)(ctx + off0) = pack2h(o[dt][0] * invA, o[dt][1] * invA);
        size_t off1 = ((size_t)(b * TSEQ + r1)) * CEMB + col;
        *(uint32_t*)(ctx + off1) = pack2h(o[dt][2] * invB, o[dt][3] * invB);
    }
}

// ---------------------------------------------------------------------------
// Launch (indices 3 AND 5 are main GEMMs for ncu capture)
// ---------------------------------------------------------------------------
static float* sym(const void* s)
{
    void* p = nullptr;
    cudaGetSymbolAddress(&p, s);
    return (float*)p;
}
static hf* symh(const void* s)
{
    void* p = nullptr;
    cudaGetSymbolAddress(&p, s);
    return (hf*)p;
}

extern "C" void kernel_launch(void* const* d_in, const int* in_sizes, int n_in,
                              void* d_out, int out_size)
{
    const float* x      = (const float*)d_in[0];
    const float* ln1_w  = (const float*)d_in[1];
    const float* ln1_b  = (const float*)d_in[2];
    const float* ln2_w  = (const float*)d_in[3];
    const float* ln2_b  = (const float*)d_in[4];
    const float* q_w    = (const float*)d_in[5];
    const float* kvd_w  = (const float*)d_in[6];
    const float* kvln_w = (const float*)d_in[7];
    const float* kvln_b = (const float*)d_in[8];
    const float* kvu_w  = (const float*)d_in[9];
    const float* proj_w = (const float*)d_in[10];
    const float* proj_b = (const float*)d_in[11];
    const float* f1_w   = (const float*)d_in[12];
    const float* f1_b   = (const float*)d_in[13];
    const float* f2_w   = (const float*)d_in[14];
    const float* f2_b   = (const float*)d_in[15];
    float* out = (float*)d_out;

    float* ckv   = sym(g_ckv);
    float* x1    = sym(g_x1);
    float* ct    = sym(g_cos);
    float* st    = sym(g_sin);
    hf *qlin  = symh(g_qlin);
    hf *kvlin = symh(g_kvlin);
    hf *hh  = symh(g_h);
    hf *cva = symh(g_ckva);
    hf *ctx = symh(g_ctx);
    hf *h2  = symh(g_h2);
    hf *ff1 = symh(g_ff1);
    hf *q = symh(g_q), *k = symh(g_k), *v = symh(g_v);
    hf *wq = symh(g_wq), *wd = symh(g_wkvd), *wu = symh(g_wkvu);
    hf *wp = symh(g_wpr), *w1 = symh(g_wf1), *w2 = symh(g_wf2);

    // 0: prep q_w
    prep_w<<<dim3(CEMB / 32, CEMB / 32), 256>>>(q_w, wq, CEMB, CEMB);
    // 1: h = LN1(x) -> fp16
    ln_k<true><<<MROWS, 256>>>(x, ln1_w, ln1_b, nullptr, hh, CEMB);
    // 2: prep kvd_w
    prep_w<<<dim3(RKV / 32, CEMB / 32), 256>>>(kvd_w, wd, CEMB, RKV);
    // 3: qlin = h @ q_w -> fp16      <-- ncu target (offset 2)
    gemm_mma<EPI_NONE, 1><<<dim3(CEMB / 128, MROWS / 128), 256>>>(
        hh, wq, nullptr, qlin, nullptr, nullptr, MROWS, CEMB, CEMB);
    // 4: prep kvu_w
    prep_w<<<dim3(2 * CEMB / 32, RKV / 32), 256>>>(kvu_w, wu, RKV, 2 * CEMB);
    // 5: ckv = h @ kvd_w (f32)       <-- ncu target (offset 0)
    gemm_mma<EPI_NONE, 0><<<dim3(RKV / 128, MROWS / 128), 256>>>(
        hh, wd, ckv, nullptr, nullptr, nullptr, MROWS, RKV, CEMB);
    // 6: ckv = LN_kv(ckv) -> fp16
    ln_k<true><<<MROWS, 256>>>(ckv, kvln_w, kvln_b, nullptr, cva, RKV);
    // 7: kvlin = ckv @ kvu_w -> fp16
    gemm_mma<EPI_NONE, 1><<<dim3(2 * CEMB / 128, MROWS / 128), 256>>>(
        cva, wu, nullptr, kvlin, nullptr, nullptr, MROWS, 2 * CEMB, RKV);
    // 8: prep proj_w
    prep_w<<<dim3(CEMB / 32, CEMB / 32), 256>>>(proj_w, wp, CEMB, CEMB);
    // 9/10: rope
    rope_tab_k<<<(TSEQ * 32 + 255) / 256, 256>>>(ct, st);
    rope_qkv_k<<<(BSZ * TSEQ * NH * 32) / 256, 256>>>(qlin, kvlin, ct, st, q, k, v);
    // 11: flash attention (double-buffered, heavy-first)
    attn_mma<<<dim3(TSEQ / 128, NH, BSZ), 256>>>(q, k, v, ctx);
    // 12: x1 = x + ctx @ proj_w + proj_b (f32)
    gemm_mma<EPI_BIAS_RESID, 0><<<dim3(CEMB / 128, MROWS / 128), 256>>>(
        ctx, wp, x1, nullptr, proj_b, x, MROWS, CEMB, CEMB);
    // 13: h2 = LN2(x1) -> fp16
    ln_k<true><<<MROWS, 256>>>(x1, ln2_w, ln2_b, nullptr, h2, CEMB);
    // 14: prep f1_w
    prep_w<<<dim3(FF / 32, CEMB / 32), 256>>>(f1_w, w1, CEMB, FF);
    // 15: ff1 = gelu(h2 @ f1_w + f1_b) -> fp16
    gemm_mma<EPI_BIAS_GELU, 1><<<dim3(FF / 128, MROWS / 128), 256>>>(
        h2, w1, nullptr, ff1, f1_b, nullptr, MROWS, FF, CEMB);
    // 16: prep f2_w
    prep_w<<<dim3(CEMB / 32, FF / 32), 256>>>(f2_w, w2, FF, CEMB);
    // 17: out = x1 + ff1 @ f2_w + f2_b (f32)
    gemm_mma<EPI_BIAS_RESID, 0><<<dim3(CEMB / 128, MROWS / 128), 256>>>(
        ff1, w2, out, nullptr, f2_b, x1, MROWS, CEMB, FF);
}

// round 17
// speedup vs baseline: 1.4286x; 1.0392x over previous
#include <cuda_runtime.h>
#include <cuda_fp16.h>
#include <math.h>
#include <stdint.h>

// ---------------------------------------------------------------------------
// Problem constants
// ---------------------------------------------------------------------------
#define BSZ   4
#define TSEQ  2048
#define CEMB  1024
#define NH    16
#define HD    64
#define RKV   512
#define FF    4096
#define MROWS (BSZ * TSEQ)   // 8192

typedef __half hf;

// ---------------------------------------------------------------------------
// Scratch (static __device__ arrays -- allocation-free per harness rules)
// ---------------------------------------------------------------------------
__device__ float g_ckv  [MROWS * RKV];
__device__ float g_x1   [MROWS * CEMB];
__device__ float g_cos  [TSEQ * 32];
__device__ float g_sin  [TSEQ * 32];
// fp16 intermediates
__device__ hf g_qlin [MROWS * CEMB];
__device__ hf g_kvlin[MROWS * 2 * CEMB];
// fp16 activations (GEMM A operands)
__device__ hf g_h   [MROWS * CEMB];
__device__ hf g_ckva[MROWS * RKV];
__device__ hf g_ctx [MROWS * CEMB];
__device__ hf g_h2  [MROWS * CEMB];
__device__ hf g_ff1 [MROWS * FF];
// q/k/v fp16, [B,H,T,D]
__device__ hf g_q[MROWS * CEMB];
__device__ hf g_k[MROWS * CEMB];
__device__ hf g_v[MROWS * CEMB];
// fp16 transposed weights [N,K]
__device__ hf g_wq [CEMB * CEMB];
__device__ hf g_wkvd[RKV * CEMB];
__device__ hf g_wkvu[2 * CEMB * RKV];
__device__ hf g_wpr[CEMB * CEMB];
__device__ hf g_wf1[FF * CEMB];
__device__ hf g_wf2[CEMB * FF];

// ---------------------------------------------------------------------------
// Helpers
// ---------------------------------------------------------------------------
__device__ __forceinline__ uint32_t pack2h(float x, float y)
{
    __half2 p = __floats2half2_rn(x, y);
    return *(uint32_t*)&p;
}
__device__ __forceinline__ float gelu_exact(float x)
{
    return 0.5f * x * (1.0f + erff(x * 0.70710678118654752f));
}
__device__ __forceinline__ void cpa16(uint32_t saddr, const void* g)
{
    asm volatile("cp.async.cg.shared.global [%0], [%1], 16;"
                 :: "r"(saddr), "l"(g) : "memory");
}
__device__ __forceinline__ void cpa_commit()
{
    asm volatile("cp.async.commit_group;" ::: "memory");
}
template <int N>
__device__ __forceinline__ void cpa_wait()
{
    asm volatile("cp.async.wait_group %0;" :: "n"(N) : "memory");
}
__device__ __forceinline__ void mma_f16(float& c0, float& c1, float& c2, float& c3,
                                        uint32_t a0, uint32_t a1, uint32_t a2,
                                        uint32_t a3, uint32_t b0, uint32_t b1)
{
    asm volatile(
        "mma.sync.aligned.m16n8k16.row.col.f32.f16.f16.f32 "
        "{%0,%1,%2,%3}, {%4,%5,%6,%7}, {%8,%9}, {%0,%1,%2,%3};"
        : "+f"(c0), "+f"(c1), "+f"(c2), "+f"(c3)
        : "r"(a0), "r"(a1), "r"(a2), "r"(a3), "r"(b0), "r"(b1));
}
__device__ __forceinline__ void ldm4(uint32_t& r0, uint32_t& r1, uint32_t& r2,
                                     uint32_t& r3, uint32_t a)
{
    asm volatile("ldmatrix.sync.aligned.m8n8.x4.shared.b16 {%0,%1,%2,%3}, [%4];"
                 : "=r"(r0), "=r"(r1), "=r"(r2), "=r"(r3) : "r"(a));
}
__device__ __forceinline__ void ldm4t(uint32_t& r0, uint32_t& r1, uint32_t& r2,
                                      uint32_t& r3, uint32_t a)
{
    asm volatile("ldmatrix.sync.aligned.m8n8.x4.trans.shared.b16 {%0,%1,%2,%3}, [%4];"
                 : "=r"(r0), "=r"(r1), "=r"(r2), "=r"(r3) : "r"(a));
}

// ---------------------------------------------------------------------------
// LayerNorm: single-float4-per-thread, row cached in registers (W <= 1024)
// ---------------------------------------------------------------------------
template <bool HOUT>
__global__ void __launch_bounds__(256) ln_k(const float* __restrict__ x,
                                            const float* __restrict__ w,
                                            const float* __restrict__ b,
                                            float* __restrict__ out,
                                            hf* __restrict__ oh, int W)
{
    size_t row = blockIdx.x;
    const float* xr = x + row * (size_t)W;

    int i = threadIdx.x << 2;
    bool act = (i < W);
    float4 v = act ? *(const float4*)(xr + i) : make_float4(0.f, 0.f, 0.f, 0.f);

    float s  = v.x + v.y + v.z + v.w;
    float s2 = v.x * v.x + v.y * v.y + v.z * v.z + v.w * v.w;

    __shared__ float sh[8][2];
    #pragma unroll
    for (int off = 16; off; off >>= 1) {
        s  += __shfl_xor_sync(0xffffffffu, s,  off);
        s2 += __shfl_xor_sync(0xffffffffu, s2, off);
    }
    int wrp = threadIdx.x >> 5, ln = threadIdx.x & 31;
    if (ln == 0) { sh[wrp][0] = s; sh[wrp][1] = s2; }
    __syncthreads();
    s = 0.f; s2 = 0.f;
    #pragma unroll
    for (int j = 0; j < 8; j++) { s += sh[j][0]; s2 += sh[j][1]; }

    float invW = 1.0f / (float)W;
    float mu   = s * invW;
    float var  = s2 * invW - mu * mu;
    float rstd = rsqrtf(var + 1e-5f);

    if (act) {
        float4 wv = *(const float4*)(w + i);
        float4 bv = *(const float4*)(b + i);
        float r0 = (v.x - mu) * rstd * wv.x + bv.x;
        float r1 = (v.y - mu) * rstd * wv.y + bv.y;
        float r2 = (v.z - mu) * rstd * wv.z + bv.z;
        float r3 = (v.w - mu) * rstd * wv.w + bv.w;
        if (!HOUT) {
            *(float4*)(out + row * (size_t)W + i) = make_float4(r0, r1, r2, r3);
        } else {
            *(uint32_t*)(oh + row * (size_t)W + i)     = pack2h(r0, r1);
            *(uint32_t*)(oh + row * (size_t)W + i + 2) = pack2h(r2, r3);
        }
    }
}

// ---------------------------------------------------------------------------
// Weight preprocess: W[K,N] -> T [N,K] fp16, vectorized.
// Tile 64(k) x 32(n). float4 reads, half2 writes. grid = (N/32, K/64).
// ---------------------------------------------------------------------------
__global__ void __launch_bounds__(256) prep_w(const float* __restrict__ W,
                                              hf* __restrict__ T,
                                              int K, int N)
{
    __shared__ float t[64][33];
    int nb = blockIdx.x * 32, kb = blockIdx.y * 64;
    int tid = threadIdx.x;
    int rr = tid >> 3, c4 = (tid & 7) << 2;
    #pragma unroll
    for (int i = 0; i < 2; i++) {
        int r = rr + i * 32;
        float4 v = *(const float4*)(W + (size_t)(kb + r) * N + nb + c4);
        t[r][c4 + 0] = v.x; t[r][c4 + 1] = v.y;
        t[r][c4 + 2] = v.z; t[r][c4 + 3] = v.w;
    }
    __syncthreads();
    int n0 = tid >> 5;
    int k2 = (tid & 31) << 1;
    #pragma unroll
    for (int i = 0; i < 4; i++) {
        int n = n0 + i * 8;
        __half2 p;
        p.x = __float2half_rn(t[k2][n]);
        p.y = __float2half_rn(t[k2 + 1][n]);
        *(uint32_t*)(T + (size_t)(nb + n) * K + kb + k2) = *(uint32_t*)&p;
    }
}

// ---------------------------------------------------------------------------
// RoPE table + fused RoPE/transpose (fp16 in) -> fp16 q/k/v [B,H,T,D]
// ---------------------------------------------------------------------------
__global__ void rope_tab_k(float* __restrict__ ct, float* __restrict__ st)
{
    int idx = blockIdx.x * blockDim.x + threadIdx.x;
    if (idx >= TSEQ * 32) return;
    int t = idx >> 5, d = idx & 31;
    float inv = (float)pow(10000.0, -(double)d / 32.0);
    float ang = (float)t * inv;
    ct[idx] = (float)cos((double)ang);
    st[idx] = (float)sin((double)ang);
}

__global__ void __launch_bounds__(256) rope_qkv_k(
    const hf* __restrict__ qlin, const hf* __restrict__ kvlin,
    const float* __restrict__ ct, const float* __restrict__ st,
    hf* __restrict__ q, hf* __restrict__ k, hf* __restrict__ v)
{
    int g = blockIdx.x * blockDim.x + threadIdx.x;
    int d = g & 31;
    int h = (g >> 5) & 15;
    int t = (g >> 9) & 2047;
    int b = g >> 20;

    float c = ct[t * 32 + d];
    float s = st[t * 32 + d];

    const hf* qlp = qlin + ((size_t)(b * TSEQ + t)) * CEMB + h * HD;
    const hf* klp = kvlin + ((size_t)(b * TSEQ + t)) * (2 * CEMB) + h * HD;
    const hf* vlp = klp + CEMB;

    size_t o = (((size_t)(b * NH + h)) * TSEQ + t) * HD;

    float q0 = __half2float(qlp[d]), q1 = __half2float(qlp[d + 32]);
    q[o + d]      = __float2half_rn(q0 * c - q1 * s);
    q[o + d + 32] = __float2half_rn(q1 * c + q0 * s);

    float k0 = __half2float(klp[d]), k1 = __half2float(klp[d + 32]);
    k[o + d]      = __float2half_rn(k0 * c - k1 * s);
    k[o + d + 32] = __float2half_rn(k1 * c + k0 * s);

    v[o + d]      = vlp[d];
    v[o + d + 32] = vlp[d + 32];
}

// ---------------------------------------------------------------------------
// mma.sync fp16 GEMM (1-pass): unchanged from Round-16 passing kernel.
// ---------------------------------------------------------------------------
#define EPI_NONE       0
#define EPI_BIAS_RESID 1
#define EPI_BIAS_GELU  2

#define ROWP   40
#define MATB   (128 * ROWP * 2)     // 10240 bytes
#define STAGEB (2 * MATB)           // A, B

template <int EPI, int HOUT>
__global__ void __launch_bounds__(256, 2) gemm_mma(
    const hf* __restrict__ A, const hf* __restrict__ B,
    float* __restrict__ C, hf* __restrict__ Ch,
    const float* __restrict__ bias, const float* __restrict__ resid,
    int M, int N, int K)
{
    __shared__ char smem_raw[2 * STAGEB];   // 40960
    uint32_t smem_u = (uint32_t)__cvta_generic_to_shared(smem_raw);

    int tid = threadIdx.x;
    int wid = tid >> 5, lid = tid & 31;
    int wm = wid & 1, wn = wid >> 1;
    int qr = lid >> 2, qc = lid & 3;
    int bm = blockIdx.y * 128, bn = blockIdx.x * 128;

    const hf* Ap = A + (size_t)bm * K;
    const hf* Bp = B + (size_t)bn * K;

    int NK = K >> 5;    // BK = 32

    int lrow = tid >> 2;
    int lc8  = (tid & 3) << 3;

    auto stage_load = [&](int kt, int buf) {
        #pragma unroll
        for (int i = 0; i < 2; i++) {
            int row = lrow + i * 64;
            size_t go = (size_t)row * K + (kt << 5) + lc8;
            uint32_t sa = smem_u + buf * STAGEB + ((uint32_t)row * ROWP + lc8) * 2u;
            cpa16(sa + 0 * MATB, Ap + go);
            cpa16(sa + 1 * MATB, Bp + go);
        }
        cpa_commit();
    };

    int arow = wm * 64 + ((lid >> 3) & 1) * 8 + (lid & 7);
    int acolb = ((lid >> 4) & 1) * 8;
    int brow = wn * 32 + ((lid >> 4) & 1) * 8 + (lid & 7);
    int bcolb = ((lid >> 3) & 1) * 8;

    float acc[4][4][4] = {};

    stage_load(0, 0);

    for (int kt = 0; kt < NK; kt++) {
        int buf = kt & 1;
        cpa_wait<0>();
        __syncthreads();
        if (kt + 1 < NK)
            stage_load(kt + 1, buf ^ 1);

        uint32_t sA = smem_u + buf * STAGEB + 0 * MATB;
        uint32_t sB = smem_u + buf * STAGEB + 1 * MATB;

        #pragma unroll
        for (int kh = 0; kh < 2; kh++) {
            int kc = kh * 16;
            uint32_t fa[4][4], fb[4][2];
            #pragma unroll
            for (int mi = 0; mi < 4; mi++)
                ldm4(fa[mi][0], fa[mi][1], fa[mi][2], fa[mi][3],
                     sA + ((uint32_t)((arow + mi * 16) * ROWP + kc + acolb)) * 2u);
            #pragma unroll
            for (int p = 0; p < 2; p++)
                ldm4(fb[2 * p][0], fb[2 * p][1], fb[2 * p + 1][0], fb[2 * p + 1][1],
                     sB + ((uint32_t)((brow + p * 16) * ROWP + kc + bcolb)) * 2u);
            #pragma unroll
            for (int ni = 0; ni < 4; ni++)
                #pragma unroll
                for (int mi = 0; mi < 4; mi++)
                    mma_f16(acc[mi][ni][0], acc[mi][ni][1],
                            acc[mi][ni][2], acc[mi][ni][3],
                            fa[mi][0], fa[mi][1], fa[mi][2], fa[mi][3],
                            fb[ni][0], fb[ni][1]);
        }
    }

    #pragma unroll
    for (int mi = 0; mi < 4; mi++) {
        #pragma unroll
        for (int ni = 0; ni < 4; ni++) {
            int col = bn + wn * 32 + ni * 8 + qc * 2;
            #pragma unroll
            for (int half = 0; half < 2; half++) {
                int row = bm + wm * 64 + mi * 16 + qr + half * 8;
                size_t off = (size_t)row * N + col;
                float v0 = acc[mi][ni][half * 2 + 0];
                float v1 = acc[mi][ni][half * 2 + 1];
                if (EPI != EPI_NONE) {
                    v0 += bias[col];
                    v1 += bias[col + 1];
                }
                if (EPI == EPI_BIAS_GELU) {
                    v0 = gelu_exact(v0);
                    v1 = gelu_exact(v1);
                }
                if (EPI == EPI_BIAS_RESID) {
                    float2 rv = *(const float2*)(resid + off);
                    v0 += rv.x; v1 += rv.y;
                }
                if (!HOUT) {
                    *(float2*)(C + off) = make_float2(v0, v1);
                } else {
                    *(uint32_t*)(Ch + off) = pack2h(v0, v1);
                }
            }
        }
    }
}

// ---------------------------------------------------------------------------
// Flash attention, fp16 mma.sync, double-buffered K/V, single sync per iter.
// Now __launch_bounds__(256, 2) to force 2 CTAs/SM.
// ---------------------------------------------------------------------------
#define APAD 72
#define KVMAT (64 * APAD * 2)    // 9216 bytes per 64x64 matrix

__global__ void __launch_bounds__(256, 2) attn_mma(
    const hf* __restrict__ q_, const hf* __restrict__ k_,
    const hf* __restrict__ v_, hf* __restrict__ ctx)
{
    __shared__ char sm[4 * KVMAT];   // 36864 bytes; buffer b at b*2*KVMAT
    uint32_t smu = (uint32_t)__cvta_generic_to_shared(sm);

    int b = blockIdx.z, h = blockIdx.y;
    int it = gridDim.x - 1 - blockIdx.x;   // heavy tiles launch first
    int t0 = it * 128;
    size_t bh = ((size_t)(b * NH + h)) * TSEQ * HD;

    int tid = threadIdx.x;
    int w = tid >> 5, lid = tid & 31;
    int qr = lid >> 2, qc = lid & 3;

    // ---- stage Q (128x64) in low smem, ldmatrix into registers ----
    {
        const hf* src = q_ + bh + (size_t)t0 * HD;
        #pragma unroll
        for (int i = 0; i < 4; i++) {
            int chunk = tid + i * 256;
            int row = chunk >> 3, c8 = (chunk & 7) << 3;
            cpa16(smu + (row * APAD + c8) * 2, src + (size_t)row * HD + c8);
        }
        cpa_commit();
        cpa_wait<0>();
    }
    __syncthreads();

    uint32_t qa[4][4];
    {
        int row = w * 16 + ((lid >> 3) & 1) * 8 + (lid & 7);
        int colb = (lid >> 4) * 8;
        #pragma unroll
        for (int ks = 0; ks < 4; ks++) {
            uint32_t off = (uint32_t)(row * APAD + colb + ks * 16) * 2;
            ldm4(qa[ks][0], qa[ks][1], qa[ks][2], qa[ks][3], smu + off);
        }
    }
    __syncthreads();   // all warps hold Q in regs before buffer 0 is overwritten

    float m_i[2] = { -1e30f, -1e30f };
    float l_i[2] = { 0.f, 0.f };
    float o[8][4] = {};
    float s[8][4];

    int nrb = ((lid >> 4) & 1) * 8 + (lid & 7);
    int ncb = ((lid >> 3) & 1) * 8;
    int srb = ((lid >> 3) & 1) * 8 + (lid & 7);
    int scb = ((lid >> 4) & 1) * 8;

    auto load_kv = [&](int kt, int bf) {
        int k0 = kt * 64;
        const hf* srcs[2] = { k_ + bh + (size_t)k0 * HD,
                              v_ + bh + (size_t)k0 * HD };
        uint32_t base = smu + (uint32_t)bf * (2 * KVMAT);
        #pragma unroll
        for (int i = 0; i < 4; i++) {
            int chunk = tid + i * 256;
            int mat = chunk >> 9;
            int wi = chunk & 511;
            int row = wi >> 3, c8 = (wi & 7) << 3;
            cpa16(base + mat * KVMAT + (row * APAD + c8) * 2,
                  srcs[mat] + (size_t)row * HD + c8);
        }
        cpa_commit();
    };

    int nk = 2 * (it + 1);
    load_kv(0, 0);   // prologue

    for (int kt = 0; kt < nk; kt++) {
        int bf = kt & 1;
        cpa_wait<0>();
        __syncthreads();
        if (kt + 1 < nk)
            load_kv(kt + 1, bf ^ 1);

        uint32_t kbase = smu + (uint32_t)bf * (2 * KVMAT);
        uint32_t vbase = kbase + KVMAT;
        int k0 = kt * 64;

        // ---- S = Q K^T ----
        #pragma unroll
        for (int nt = 0; nt < 8; nt++) {
            s[nt][0] = 0.f; s[nt][1] = 0.f; s[nt][2] = 0.f; s[nt][3] = 0.f;
        }
        #pragma unroll
        for (int ks = 0; ks < 4; ks++) {
            uint32_t kb[8][2];
            #pragma unroll
            for (int g = 0; g < 4; g++) {
                uint32_t a = kbase +
                             (uint32_t)((g * 16 + nrb) * APAD + ks * 16 + ncb) * 2;
                ldm4(kb[2 * g][0], kb[2 * g][1], kb[2 * g + 1][0], kb[2 * g + 1][1], a);
            }
            #pragma unroll
            for (int nt = 0; nt < 8; nt++)
                mma_f16(s[nt][0], s[nt][1], s[nt][2], s[nt][3],
                        qa[ks][0], qa[ks][1], qa[ks][2], qa[ks][3],
                        kb[nt][0], kb[nt][1]);
        }

        int row0 = t0 + w * 16 + qr;
        int row1 = row0 + 8;
        #pragma unroll
        for (int nt = 0; nt < 8; nt++) {
            int col0 = k0 + nt * 8 + qc * 2;
            s[nt][0] = (col0     > row0) ? -1e30f : s[nt][0] * 0.125f;
            s[nt][1] = (col0 + 1 > row0) ? -1e30f : s[nt][1] * 0.125f;
            s[nt][2] = (col0     > row1) ? -1e30f : s[nt][2] * 0.125f;
            s[nt][3] = (col0 + 1 > row1) ? -1e30f : s[nt][3] * 0.125f;
        }

        float mxA = -1e30f, mxB = -1e30f;
        #pragma unroll
        for (int nt = 0; nt < 8; nt++) {
            mxA = fmaxf(mxA, fmaxf(s[nt][0], s[nt][1]));
            mxB = fmaxf(mxB, fmaxf(s[nt][2], s[nt][3]));
        }
        mxA = fmaxf(mxA, __shfl_xor_sync(0xffffffffu, mxA, 1));
        mxA = fmaxf(mxA, __shfl_xor_sync(0xffffffffu, mxA, 2));
        mxB = fmaxf(mxB, __shfl_xor_sync(0xffffffffu, mxB, 1));
        mxB = fmaxf(mxB, __shfl_xor_sync(0xffffffffu, mxB, 2));

        float mnA = fmaxf(m_i[0], mxA), mnB = fmaxf(m_i[1], mxB);
        float aA = expf(m_i[0] - mnA), aB = expf(m_i[1] - mnB);
        m_i[0] = mnA; m_i[1] = mnB;

        float sumA = 0.f, sumB = 0.f;
        #pragma unroll
        for (int nt = 0; nt < 8; nt++) {
            s[nt][0] = expf(s[nt][0] - mnA); sumA += s[nt][0];
            s[nt][1] = expf(s[nt][1] - mnA); sumA += s[nt][1];
            s[nt][2] = expf(s[nt][2] - mnB); sumB += s[nt][2];
            s[nt][3] = expf(s[nt][3] - mnB); sumB += s[nt][3];
        }
        sumA += __shfl_xor_sync(0xffffffffu, sumA, 1);
        sumA += __shfl_xor_sync(0xffffffffu, sumA, 2);
        sumB += __shfl_xor_sync(0xffffffffu, sumB, 1);
        sumB += __shfl_xor_sync(0xffffffffu, sumB, 2);
        l_i[0] = l_i[0] * aA + sumA;
        l_i[1] = l_i[1] * aB + sumB;

        #pragma unroll
        for (int dt = 0; dt < 8; dt++) {
            o[dt][0] *= aA; o[dt][1] *= aA;
            o[dt][2] *= aB; o[dt][3] *= aB;
        }

        // ---- O += P V ----
        #pragma unroll
        for (int ks = 0; ks < 4; ks++) {
            uint32_t pa[4];
            pa[0] = pack2h(s[2 * ks][0],     s[2 * ks][1]);
            pa[1] = pack2h(s[2 * ks][2],     s[2 * ks][3]);
            pa[2] = pack2h(s[2 * ks + 1][0], s[2 * ks + 1][1]);
            pa[3] = pack2h(s[2 * ks + 1][2], s[2 * ks + 1][3]);

            uint32_t vb[8][2];
            #pragma unroll
            for (int g = 0; g < 4; g++) {
                uint32_t a = vbase +
                             (uint32_t)((ks * 16 + srb) * APAD + g * 16 + scb) * 2;
                ldm4t(vb[2 * g][0], vb[2 * g][1], vb[2 * g + 1][0], vb[2 * g + 1][1], a);
            }
            #pragma unroll
            for (int dt = 0; dt < 8; dt++)
                mma_f16(o[dt][0], o[dt][1], o[dt][2], o[dt][3],
                        pa[0], pa[1], pa[2], pa[3], vb[dt][0], vb[dt][1]);
        }
    }

    float invA = 1.0f / l_i[0], invB = 1.0f / l_i[1];
    int r0 = t0 + w * 16 + qr, r1 = r0 + 8;
    #pragma unroll
    for (int dt = 0; dt < 8; dt++) {
        int col = h * HD + dt * 8 + qc * 2;
        size_t off0 = ((size_t)(b * TSEQ + r0)) * CEMB + col;
        *(uint32_t*)(ctx + off0) = pack2h(o[dt][0] * invA, o[dt][1] * invA);
        size_t off1 = ((size_t)(b * TSEQ + r1)) * CEMB + col;
        *(uint32_t*)(ctx + off1) = pack2h(o[dt][2] * invB, o[dt][3] * invB);
    }
}

// ---------------------------------------------------------------------------
// Launch (indices 3 AND 5 are main GEMMs for ncu capture)
// ---------------------------------------------------------------------------
static float* sym(const void* s)
{
    void* p = nullptr;
    cudaGetSymbolAddress(&p, s);
    return (float*)p;
}
static hf* symh(const void* s)
{
    void* p = nullptr;
    cudaGetSymbolAddress(&p, s);
    return (hf*)p;
}

extern "C" void kernel_launch(void* const* d_in, const int* in_sizes, int n_in,
                              void* d_out, int out_size)
{
    const float* x      = (const float*)d_in[0];
    const float* ln1_w  = (const float*)d_in[1];
    const float* ln1_b  = (const float*)d_in[2];
    const float* ln2_w  = (const float*)d_in[3];
    const float* ln2_b  = (const float*)d_in[4];
    const float* q_w    = (const float*)d_in[5];
    const float* kvd_w  = (const float*)d_in[6];
    const float* kvln_w = (const float*)d_in[7];
    const float* kvln_b = (const float*)d_in[8];
    const float* kvu_w  = (const float*)d_in[9];
    const float* proj_w = (const float*)d_in[10];
    const float* proj_b = (const float*)d_in[11];
    const float* f1_w   = (const float*)d_in[12];
    const float* f1_b   = (const float*)d_in[13];
    const float* f2_w   = (const float*)d_in[14];
    const float* f2_b   = (const float*)d_in[15];
    float* out = (float*)d_out;

    float* ckv   = sym(g_ckv);
    float* x1    = sym(g_x1);
    float* ct    = sym(g_cos);
    float* st    = sym(g_sin);
    hf *qlin  = symh(g_qlin);
    hf *kvlin = symh(g_kvlin);
    hf *hh  = symh(g_h);
    hf *cva = symh(g_ckva);
    hf *ctx = symh(g_ctx);
    hf *h2  = symh(g_h2);
    hf *ff1 = symh(g_ff1);
    hf *q = symh(g_q), *k = symh(g_k), *v = symh(g_v);
    hf *wq = symh(g_wq), *wd = symh(g_wkvd), *wu = symh(g_wkvu);
    hf *wp = symh(g_wpr), *w1 = symh(g_wf1), *w2 = symh(g_wf2);

    // 0: prep q_w
    prep_w<<<dim3(CEMB / 32, CEMB / 64), 256>>>(q_w, wq, CEMB, CEMB);
    // 1: h = LN1(x) -> fp16
    ln_k<true><<<MROWS, 256>>>(x, ln1_w, ln1_b, nullptr, hh, CEMB);
    // 2: prep kvd_w
    prep_w<<<dim3(RKV / 32, CEMB / 64), 256>>>(kvd_w, wd, CEMB, RKV);
    // 3: qlin = h @ q_w -> fp16      <-- ncu target (offset 2)
    gemm_mma<EPI_NONE, 1><<<dim3(CEMB / 128, MROWS / 128), 256>>>(
        hh, wq, nullptr, qlin, nullptr, nullptr, MROWS, CEMB, CEMB);
    // 4: prep kvu_w
    prep_w<<<dim3(2 * CEMB / 32, RKV / 64), 256>>>(kvu_w, wu, RKV, 2 * CEMB);
    // 5: ckv = h @ kvd_w (f32)       <-- ncu target (offset 0)
    gemm_mma<EPI_NONE, 0><<<dim3(RKV / 128, MROWS / 128), 256>>>(
        hh, wd, ckv, nullptr, nullptr, nullptr, MROWS, RKV, CEMB);
    // 6: ckv = LN_kv(ckv) -> fp16
    ln_k<true><<<MROWS, 256>>>(ckv, kvln_w, kvln_b, nullptr, cva, RKV);
    // 7: kvlin = ckv @ kvu_w -> fp16
    gemm_mma<EPI_NONE, 1><<<dim3(2 * CEMB / 128, MROWS / 128), 256>>>(
        cva, wu, nullptr, kvlin, nullptr, nullptr, MROWS, 2 * CEMB, RKV);
    // 8: prep proj_w
    prep_w<<<dim3(CEMB / 32, CEMB / 64), 256>>>(proj_w, wp, CEMB, CEMB);
    // 9/10: rope
    rope_tab_k<<<(TSEQ * 32 + 255) / 256, 256>>>(ct, st);
    rope_qkv_k<<<(BSZ * TSEQ * NH * 32) / 256, 256>>>(qlin, kvlin, ct, st, q, k, v);
    // 11: flash attention (double-buffered, heavy-first, 2 CTAs/SM)
    attn_mma<<<dim3(TSEQ / 128, NH, BSZ), 256>>>(q, k, v, ctx);
    // 12: x1 = x + ctx @ proj_w + proj_b (f32)
    gemm_mma<EPI_BIAS_RESID, 0><<<dim3(CEMB / 128, MROWS / 128), 256>>>(
        ctx, wp, x1, nullptr, proj_b, x, MROWS, CEMB, CEMB);
    // 13: h2 = LN2(x1) -> fp16
    ln_k<true><<<MROWS, 256>>>(x1, ln2_w, ln2_b, nullptr, h2, CEMB);
    // 14: prep f1_w
    prep_w<<<dim3(FF / 32, CEMB / 64), 256>>>(f1_w, w1, CEMB, FF);
    // 15: ff1 = gelu(h2 @ f1_w + f1_b) -> fp16
    gemm_mma<EPI_BIAS_GELU, 1><<<dim3(FF / 128, MROWS / 128), 256>>>(
        h2, w1, nullptr, ff1, f1_b, nullptr, MROWS, FF, CEMB);
    // 16: prep f2_w
    prep_w<<<dim3(CEMB / 32, FF / 64), 256>>>(f2_w, w2, FF, CEMB);
    // 17: out = x1 + ff1 @ f2_w + f2_b (f32)
    gemm_mma<EPI_BIAS_RESID, 0><<<dim3(CEMB / 128, MROWS / 128), 256>>>(
        ff1, w2, out, nullptr, f2_b, x1, MROWS, CEMB, FF);
}